// round 1
// baseline (speedup 1.0000x reference)
#include <cuda_runtime.h>
#include <cstdint>

#define EMB 300
#define BATCH 256
#define NNODE 64

// ---------------- scratch (static device memory; no allocation) --------------
__device__ float g_h[2 * BATCH * NNODE * EMB];   // node states per (tree,b,n)
__device__ float g_t[2 * BATCH * NNODE * EMB];   // transformed child values
__device__ float g_rep[2 * BATCH * EMB];         // sum-pooled reps
__device__ float g_x[BATCH * 1800];              // MLP input
__device__ float g_acc0[5 * BATCH * 600];        // layer0 k-split partials (z=5)
__device__ float g_acc1[2 * BATCH * 600];        // layer1 partials (z=2)
__device__ float g_acc2[2 * BATCH * 600];        // layer2 partials (z=2)
__device__ float g_y0[BATCH * 600];
__device__ float g_y1[BATCH * 600];
__device__ float g_y2[BATCH * 600];
__device__ int   g_rows[9][22016];               // compacted (level,rel) row lists
__device__ int   g_cnt[9];

// ---------------- f32x2 helpers (FFMA2: 2x fp32 FMA throughput) --------------
__device__ __forceinline__ unsigned long long pk(float lo, float hi) {
    unsigned long long r;
    asm("mov.b64 %0,{%1,%2};" : "=l"(r) : "f"(lo), "f"(hi));
    return r;
}
__device__ __forceinline__ void upk(unsigned long long v, float& lo, float& hi) {
    asm("mov.b64 {%0,%1},%2;" : "=f"(lo), "=f"(hi) : "l"(v));
}
__device__ __forceinline__ void ffma2(unsigned long long& d, unsigned long long a,
                                      unsigned long long b) {
    asm("fma.rn.f32x2 %0,%1,%2,%0;" : "+l"(d) : "l"(a), "l"(b));
}

// ---------------- 1. embeddings: rep sums + leaf word vectors ----------------
__global__ void embed_kernel(const int* __restrict__ px, const int* __restrict__ hx,
                             const int* __restrict__ pwi, const int* __restrict__ hwi,
                             const float* __restrict__ E) {
    int tree = blockIdx.x, b = blockIdx.y;
    const int* x  = (tree ? hx : px) + b * 64;
    const int* wi = (tree ? hwi : pwi) + b * 64;
    __shared__ int sx[64], swi[64];
    int tid = threadIdx.x;
    if (tid < 64) { sx[tid] = x[tid]; swi[tid] = wi[tid]; }
    __syncthreads();
    if (tid >= EMB) return;
    float rep = 0.f;
#pragma unroll 8
    for (int s = 0; s < 64; s++) rep += __ldg(&E[(size_t)sx[s] * EMB + tid]);
    g_rep[((size_t)tree * BATCH + b) * EMB + tid] = rep;
    float* hb = g_h + ((size_t)(tree * BATCH + b) * NNODE) * EMB;
    for (int n = 0; n < 64; n++) {
        int w = swi[n];
        hb[n * EMB + tid] = (w < 0) ? 1.0f : E[(size_t)sx[w] * EMB + tid];
    }
}

// ---------------- 2. deterministic compaction per (level, rel) ---------------
__global__ void compact_kernel(const int* __restrict__ prel, const int* __restrict__ hrel) {
    int li = blockIdx.x;
    int l = li / 3, r = li % 3;
    int n0, nc;
    if (l == 0)      { n0 = 1;  nc = 4;  }   // level 1
    else if (l == 1) { n0 = 5;  nc = 16; }   // level 2
    else             { n0 = 21; nc = 43; }   // level 3
    int total = 512 * nc;
    __shared__ int wsum[32];
    __shared__ int sbase, stotal;
    int tid = threadIdx.x, lane = tid & 31, wid = tid >> 5;
    if (tid == 0) sbase = 0;
    __syncthreads();
    for (int start = 0; start < total; start += 1024) {
        int i = start + tid;
        int flag = 0, v = 0;
        if (i < total) {
            int tb = i / nc;
            int n = n0 + (i - tb * nc);
            int tree = tb >> 8, b = tb & 255;
            const int* rel = tree ? hrel : prel;
            flag = (rel[b * 64 + n] == r);
            v = (tb << 6) | n;   // meta = (tree*256+b)*64 + n encoded compactly
        }
        unsigned m = __ballot_sync(0xffffffffu, flag != 0);
        int within = __popc(m & ((1u << lane) - 1));
        if (lane == 0) wsum[wid] = __popc(m);
        __syncthreads();
        if (wid == 0) {
            int val = wsum[lane];
            int orig = val;
            for (int o = 1; o < 32; o <<= 1) {
                int t = __shfl_up_sync(0xffffffffu, val, o);
                if (lane >= o) val += t;
            }
            wsum[lane] = val - orig;          // exclusive scan
            if (lane == 31) stotal = val;     // inclusive total
        }
        __syncthreads();
        if (flag) g_rows[li][sbase + wsum[wid] + within] = v;
        __syncthreads();
        if (tid == 0) sbase += stotal;
        __syncthreads();
    }
    if (tid == 0) g_cnt[li] = sbase;
}

// ---------------- 3. gathered GEMM: t = h @ W_enc[r]^T for listed rows -------
// Rows gathered via g_rows; t written to g_t (row stride EMB). FFMA2 inner loop.
template <int TM>
__global__ void __launch_bounds__(256) tree_gemm(const float* __restrict__ Wenc, int l) {
    constexpr int TILEM = 8 * TM;
    int r = blockIdx.y;
    int li = l * 3 + r;
    int cnt = g_cnt[li];
    int row0 = blockIdx.x * TILEM;
    if (row0 >= cnt) return;
    const float* W = Wenc + (size_t)r * EMB * EMB;
    __shared__ float As[TILEM][17];
    __shared__ float Ws[EMB][17];
    __shared__ int meta[TILEM];
    int tid = threadIdx.x, lane = tid & 31, warp = tid >> 5;
    if (tid < TILEM) {
        int rr = row0 + tid;
        meta[tid] = (rr < cnt) ? g_rows[li][rr] : -1;
    }
    __syncthreads();
    unsigned long long acc[TM][5];
#pragma unroll
    for (int i = 0; i < TM; i++)
#pragma unroll
        for (int j = 0; j < 5; j++) acc[i][j] = 0ull;

    for (int k0 = 0; k0 < EMB; k0 += 16) {
        int kc = EMB - k0; if (kc > 16) kc = 16;   // 16 or 12
        int kc4 = kc >> 2;
        __syncthreads();
        for (int i = tid; i < TILEM * kc4; i += 256) {
            int m = i / kc4, q = i - m * kc4;
            float4 v = make_float4(0.f, 0.f, 0.f, 0.f);
            int mm = meta[m];
            if (mm >= 0)
                v = *reinterpret_cast<const float4*>(g_h + (size_t)mm * EMB + k0 + 4 * q);
            As[m][4 * q + 0] = v.x; As[m][4 * q + 1] = v.y;
            As[m][4 * q + 2] = v.z; As[m][4 * q + 3] = v.w;
        }
        for (int i = tid; i < EMB * kc4; i += 256) {
            int f = i / kc4, q = i - f * kc4;
            float4 v = *reinterpret_cast<const float4*>(W + (size_t)f * EMB + k0 + 4 * q);
            Ws[f][4 * q + 0] = v.x; Ws[f][4 * q + 1] = v.y;
            Ws[f][4 * q + 2] = v.z; Ws[f][4 * q + 3] = v.w;
        }
        __syncthreads();
#pragma unroll 4
        for (int kk = 0; kk < kc; kk++) {
            unsigned long long a2[TM];
#pragma unroll
            for (int i = 0; i < TM; i++) {
                float a = As[warp * TM + i][kk];
                a2[i] = pk(a, a);
            }
            unsigned long long w2[5];
#pragma unroll
            for (int j = 0; j < 5; j++) {
                int f0 = lane + 64 * j;                  // <= 287, always valid
                float wlo = Ws[f0][kk];
                float whi = (f0 + 32 < EMB) ? Ws[f0 + 32][kk] : 0.f;
                w2[j] = pk(wlo, whi);
            }
#pragma unroll
            for (int i = 0; i < TM; i++)
#pragma unroll
                for (int j = 0; j < 5; j++) ffma2(acc[i][j], a2[i], w2[j]);
        }
    }
#pragma unroll
    for (int i = 0; i < TM; i++) {
        int mm = meta[warp * TM + i];
        if (mm < 0) continue;
        float* o = g_t + (size_t)mm * EMB;
#pragma unroll
        for (int j = 0; j < 5; j++) {
            float lo, hi; upk(acc[i][j], lo, hi);
            int f0 = lane + 64 * j;
            o[f0] = lo;
            if (f0 + 32 < EMB) o[f0 + 32] = hi;
        }
    }
}

// ---------------- 4. combine: h[p] = relu(h[p] * mean(children)) -------------
// Tree structure is fixed: children of p are 4p+1..min(4p+4,63).
__global__ void update_kernel(const int* __restrict__ prel, const int* __restrict__ hrel,
                              int plo, int phi) {
    int tree = blockIdx.x, b = blockIdx.y;
    int e = threadIdx.x;
    if (e >= EMB) return;
    const int* rel = (tree ? hrel : prel) + b * 64;
    float* hb = g_h + ((size_t)(tree * BATCH + b) * NNODE) * EMB;
    const float* tb = g_t + ((size_t)(tree * BATCH + b) * NNODE) * EMB;
    for (int p = plo; p <= phi; p++) {
        int c0 = 4 * p + 1;
        int c1 = 4 * p + 4; if (c1 > 63) c1 = 63;
        float s = 0.f;
        for (int c = c0; c <= c1; c++) {
            unsigned rid = (unsigned)rel[c];
            s += (rid <= 2u) ? tb[c * EMB + e] : hb[c * EMB + e];
        }
        float mean = s / (float)(c1 - c0 + 1);
        float v = hb[p * EMB + e] * mean;
        hb[p * EMB + e] = v > 0.f ? v : 0.f;
    }
}

// ---------------- 5. MLP input construction ----------------------------------
__global__ void build_x_kernel() {
    int b = blockIdx.x;
    int e = threadIdx.x;
    if (e >= EMB) return;
    float pr = g_rep[b * EMB + e];
    float hr = g_rep[(BATCH + b) * EMB + e];
    float ps = g_h[((size_t)b * NNODE) * EMB + e];
    float hs = g_h[((size_t)(BATCH + b) * NNODE) * EMB + e];
    float* x = g_x + (size_t)b * 1800;
    x[e] = pr; x[300 + e] = hr; x[600 + e] = pr - hr; x[900 + e] = pr * hr;
    x[1200 + e] = ps - hs; x[1500 + e] = ps * hs;
}

// ---------------- 6. MLP GEMM: k-split partials into slabs (no atomics) ------
// grid: (32 m-tiles of 8 rows, 2 f-slices of 300, z k-splits). sel picks bufs.
__global__ void __launch_bounds__(256) fc_gemm(int sel, int lda, int K, int Ksub,
                                               const float* __restrict__ Wt) {
    const float* A = (sel == 0) ? g_x : (sel == 1) ? g_y0 : g_y1;
    float* out = (sel == 0) ? g_acc0 : (sel == 1) ? g_acc1 : g_acc2;
    int m0 = blockIdx.x * 8;
    int fs = blockIdx.y * 300;
    int z = blockIdx.z;
    int kbeg = z * Ksub, kend = kbeg + Ksub;
    const float* W = Wt + (size_t)fs * K;
    __shared__ float As[8][17];
    __shared__ float Ws[300][17];
    int tid = threadIdx.x, lane = tid & 31, warp = tid >> 5;
    unsigned long long acc[5] = {0ull, 0ull, 0ull, 0ull, 0ull};
    for (int k0 = kbeg; k0 < kend; k0 += 16) {
        int kc = kend - k0; if (kc > 16) kc = 16;   // multiples of 4 by construction
        int kc4 = kc >> 2;
        __syncthreads();
        for (int i = tid; i < 8 * kc4; i += 256) {
            int m = i / kc4, q = i - m * kc4;
            float4 v = *reinterpret_cast<const float4*>(A + (size_t)(m0 + m) * lda + k0 + 4 * q);
            As[m][4 * q + 0] = v.x; As[m][4 * q + 1] = v.y;
            As[m][4 * q + 2] = v.z; As[m][4 * q + 3] = v.w;
        }
        for (int i = tid; i < 300 * kc4; i += 256) {
            int f = i / kc4, q = i - f * kc4;
            float4 v = *reinterpret_cast<const float4*>(W + (size_t)f * K + k0 + 4 * q);
            Ws[f][4 * q + 0] = v.x; Ws[f][4 * q + 1] = v.y;
            Ws[f][4 * q + 2] = v.z; Ws[f][4 * q + 3] = v.w;
        }
        __syncthreads();
#pragma unroll 4
        for (int kk = 0; kk < kc; kk++) {
            float a = As[warp][kk];
            unsigned long long a2 = pk(a, a);
#pragma unroll
            for (int j = 0; j < 5; j++) {
                int f0 = lane + 64 * j;
                float wlo = Ws[f0][kk];
                float whi = (f0 + 32 < 300) ? Ws[f0 + 32][kk] : 0.f;
                ffma2(acc[j], a2, pk(wlo, whi));
            }
        }
    }
    float* o = out + (size_t)z * BATCH * 600 + (size_t)(m0 + warp) * 600 + fs;
#pragma unroll
    for (int j = 0; j < 5; j++) {
        float lo, hi; upk(acc[j], lo, hi);
        int f0 = lane + 64 * j;
        o[f0] = lo;
        if (f0 + 32 < 300) o[f0 + 32] = hi;
    }
}

// ---------------- 7. reduce k-split slabs + bias + relu ----------------------
__global__ void bias_relu_kernel(const float* __restrict__ bias, int sel, int nz) {
    int b = blockIdx.x, n = threadIdx.x;
    const float* acc = (sel == 0) ? g_acc0 : (sel == 1) ? g_acc1 : g_acc2;
    float s = bias[n];
    for (int z = 0; z < nz; z++) s += acc[(size_t)z * BATCH * 600 + b * 600 + n];
    float v = s > 0.f ? s : 0.f;
    float* y = (sel == 0) ? g_y0 : (sel == 1) ? g_y1 : g_y2;
    y[b * 600 + n] = v;
}

// ---------------- 8. output layer [256,3] ------------------------------------
__global__ void out_kernel(const float* __restrict__ Wout, const float* __restrict__ bout,
                           float* __restrict__ out) {
    int b = blockIdx.x;
    int w = threadIdx.x >> 5, lane = threadIdx.x & 31;
    if (w >= 3) return;
    float s = 0.f;
    for (int k = lane; k < 600; k += 32)
        s += g_y2[b * 600 + k] * Wout[w * 600 + k];
    for (int o = 16; o; o >>= 1) s += __shfl_down_sync(0xffffffffu, s, o);
    if (lane == 0) out[b * 3 + w] = s + bout[w];
}

// ---------------- launch ------------------------------------------------------
extern "C" void kernel_launch(void* const* d_in, const int* in_sizes, int n_in,
                              void* d_out, int out_size) {
    const int*   px   = (const int*)d_in[0];
    const int*   hx   = (const int*)d_in[1];
    const int*   pwi  = (const int*)d_in[2];
    const int*   prel = (const int*)d_in[3];
    const int*   hwi  = (const int*)d_in[4];
    const int*   hrel = (const int*)d_in[5];
    // d_in[6]=parent, d_in[7]=level (structure is fixed; hardcoded)
    const float* E    = (const float*)d_in[8];
    const float* Wenc = (const float*)d_in[9];
    const float* W0w  = (const float*)d_in[10];
    const float* W0b  = (const float*)d_in[11];
    const float* W1w  = (const float*)d_in[12];
    const float* W1b  = (const float*)d_in[13];
    const float* W2w  = (const float*)d_in[14];
    const float* W2b  = (const float*)d_in[15];
    const float* Wow  = (const float*)d_in[16];
    const float* Wob  = (const float*)d_in[17];
    float* out = (float*)d_out;

    embed_kernel<<<dim3(2, 256), 320>>>(px, hx, pwi, hwi, E);
    compact_kernel<<<9, 1024>>>(prel, hrel);

    // level 3 (children 21..63 -> parents 5..15)
    tree_gemm<8><<<dim3(344, 3), 256>>>(Wenc, 2);
    update_kernel<<<dim3(2, 256), 320>>>(prel, hrel, 5, 15);
    // level 2 (children 5..20 -> parents 1..4)
    tree_gemm<2><<<dim3(512, 3), 256>>>(Wenc, 1);
    update_kernel<<<dim3(2, 256), 320>>>(prel, hrel, 1, 4);
    // level 1 (children 1..4 -> parent 0)
    tree_gemm<1><<<dim3(256, 3), 256>>>(Wenc, 0);
    update_kernel<<<dim3(2, 256), 320>>>(prel, hrel, 0, 0);

    build_x_kernel<<<256, 320>>>();

    // layer0: K=1800, 5-way k-split (Ksub=360)
    fc_gemm<<<dim3(32, 2, 5), 256>>>(0, 1800, 1800, 360, W0w);
    bias_relu_kernel<<<256, 600>>>(W0b, 0, 5);
    // layer1: K=600, 2-way split (Ksub=300)
    fc_gemm<<<dim3(32, 2, 2), 256>>>(1, 600, 600, 300, W1w);
    bias_relu_kernel<<<256, 600>>>(W1b, 1, 2);
    // layer2
    fc_gemm<<<dim3(32, 2, 2), 256>>>(2, 600, 600, 300, W2w);
    bias_relu_kernel<<<256, 600>>>(W2b, 2, 2);

    out_kernel<<<256, 96>>>(Wow, Wob, out);
}

// round 2
// speedup vs baseline: 1.5835x; 1.5835x over previous
#include <cuda_runtime.h>
#include <cstdint>

#define EMB 300
#define HSTR 304          // padded k-stride for h/t rows (19 x 16)
#define BATCH 256
#define NNODE 64

// ---------------- scratch (static device memory; zero-initialized) -----------
__device__ float g_h[2 * BATCH * NNODE * HSTR];   // node states (padded rows)
__device__ float g_t[2 * BATCH * NNODE * HSTR];   // transformed child values
__device__ float g_rep[2 * BATCH * EMB];          // sum-pooled reps
__device__ float g_x[BATCH * 1808];               // MLP input (padded 1800->1808)
__device__ float g_y0[BATCH * 608];
__device__ float g_y1[BATCH * 608];
__device__ float g_y2[BATCH * 608];
__device__ float g_acc0[5 * BATCH * 600];
__device__ float g_acc1[2 * BATCH * 600];
__device__ float g_acc2[2 * BATCH * 600];
__device__ float g_Wencp[3 * 300 * HSTR];         // zero-padded W_enc
__device__ float g_W0p[600 * 1808];               // zero-padded W0
__device__ float g_W12p[2 * 600 * 608];           // zero-padded W1,W2
__device__ int   g_rows[9][22016];
__device__ int   g_cnt[9];

// ---------------- helpers -----------------------------------------------------
__device__ __forceinline__ unsigned long long pk(float lo, float hi) {
    unsigned long long r;
    asm("mov.b64 %0,{%1,%2};" : "=l"(r) : "f"(lo), "f"(hi));
    return r;
}
__device__ __forceinline__ void upk(unsigned long long v, float& lo, float& hi) {
    asm("mov.b64 {%0,%1},%2;" : "=f"(lo), "=f"(hi) : "l"(v));
}
__device__ __forceinline__ void ffma2(unsigned long long& d, unsigned long long a,
                                      unsigned long long b) {
    asm("fma.rn.f32x2 %0,%1,%2,%0;" : "+l"(d) : "l"(a), "l"(b));
}
__device__ __forceinline__ uint32_t s2u(const void* p) {
    return (uint32_t)__cvta_generic_to_shared(p);
}
__device__ __forceinline__ void cpa4(uint32_t s, const float* g) {
    asm volatile("cp.async.ca.shared.global [%0],[%1],4;" :: "r"(s), "l"(g));
}
__device__ __forceinline__ void cpa_commit() {
    asm volatile("cp.async.commit_group;");
}
template <int N> __device__ __forceinline__ void cpa_wait() {
    asm volatile("cp.async.wait_group %0;" :: "n"(N));
}

// ---------------- weight padding kernels --------------------------------------
__global__ void pad_enc(const float* __restrict__ W) {
    int i = blockIdx.x;          // r*300+f, 0..899
    int k = threadIdx.x;         // 0..303
    g_Wencp[i * HSTR + k] = (k < 300) ? W[(size_t)i * 300 + k] : 0.f;
}
__global__ void pad_w0(const float* __restrict__ W0) {
    int f = blockIdx.x;          // 0..599
    for (int k = threadIdx.x; k < 1808; k += blockDim.x)
        g_W0p[(size_t)f * 1808 + k] = (k < 1800) ? W0[(size_t)f * 1800 + k] : 0.f;
}
__global__ void pad_w12(const float* __restrict__ W1, const float* __restrict__ W2) {
    int bi = blockIdx.x;         // 0..1199
    int which = bi / 600, f = bi % 600;
    const float* W = which ? W2 : W1;
    int k = threadIdx.x;         // 0..607
    g_W12p[((size_t)which * 600 + f) * 608 + k] = (k < 600) ? W[(size_t)f * 600 + k] : 0.f;
}

// ---------------- embeddings ---------------------------------------------------
__global__ void rep_kernel(const int* __restrict__ px, const int* __restrict__ hx,
                           const float* __restrict__ E) {
    int b = blockIdx.x, tree = blockIdx.y;
    const int* x = (tree ? hx : px) + b * 64;
    __shared__ int sx[64];
    int tid = threadIdx.x;
    if (tid < 64) sx[tid] = x[tid];
    __syncthreads();
    if (tid >= EMB) return;
    float rep = 0.f;
#pragma unroll 8
    for (int s = 0; s < 64; s++) rep += __ldg(&E[(size_t)sx[s] * EMB + tid]);
    g_rep[((size_t)tree * BATCH + b) * EMB + tid] = rep;
}

__global__ void leaf_kernel(const int* __restrict__ px, const int* __restrict__ hx,
                            const int* __restrict__ pwi, const int* __restrict__ hwi,
                            const float* __restrict__ E) {
    int b = blockIdx.x, tree = blockIdx.y;
    const int* x  = (tree ? hx : px) + b * 64;
    const int* wi = (tree ? hwi : pwi) + b * 64;
    __shared__ int sx[64], swi[64];
    int tid = threadIdx.x;
    if (tid < 64) { sx[tid] = x[tid]; swi[tid] = wi[tid]; }
    __syncthreads();
    if (tid >= HSTR) return;
    float* hb = g_h + ((size_t)(tree * BATCH + b) * NNODE) * HSTR;
    if (tid >= EMB) {            // keep pad columns zero (defensive)
        for (int n = 0; n < 64; n++) hb[n * HSTR + tid] = 0.f;
        return;
    }
    for (int n = 0; n < 64; n++) {
        int w = swi[n];
        hb[n * HSTR + tid] = (w < 0) ? 1.0f : E[(size_t)sx[w] * EMB + tid];
    }
}

// ---------------- compaction per (level, rel) ----------------------------------
__global__ void compact_kernel(const int* __restrict__ prel, const int* __restrict__ hrel) {
    int li = blockIdx.x;
    int l = li / 3, r = li % 3;
    int n0, nc;
    if (l == 0)      { n0 = 1;  nc = 4;  }
    else if (l == 1) { n0 = 5;  nc = 16; }
    else             { n0 = 21; nc = 43; }
    int total = 512 * nc;
    __shared__ int wsum[32];
    __shared__ int sbase, stotal;
    int tid = threadIdx.x, lane = tid & 31, wid = tid >> 5;
    if (tid == 0) sbase = 0;
    __syncthreads();
    for (int start = 0; start < total; start += 1024) {
        int i = start + tid;
        int flag = 0, v = 0;
        if (i < total) {
            int tb = i / nc;
            int n = n0 + (i - tb * nc);
            int tree = tb >> 8, b = tb & 255;
            const int* rel = tree ? hrel : prel;
            flag = (rel[b * 64 + n] == r);
            v = (tb << 6) | n;
        }
        unsigned m = __ballot_sync(0xffffffffu, flag != 0);
        int within = __popc(m & ((1u << lane) - 1));
        if (lane == 0) wsum[wid] = __popc(m);
        __syncthreads();
        if (wid == 0) {
            int val = wsum[lane], orig = val;
            for (int o = 1; o < 32; o <<= 1) {
                int t = __shfl_up_sync(0xffffffffu, val, o);
                if (lane >= o) val += t;
            }
            wsum[lane] = val - orig;
            if (lane == 31) stotal = val;
        }
        __syncthreads();
        if (flag) g_rows[li][sbase + wsum[wid] + within] = v;
        __syncthreads();
        if (tid == 0) sbase += stotal;
        __syncthreads();
    }
    if (tid == 0) g_cnt[li] = sbase;
}

// ---------------- gathered GEMM with cp.async double buffering ------------------
// t = h @ W_enc[r]^T for compacted rows. K padded to 304 = 19 tiles of 16.
template <int TM>
__global__ void __launch_bounds__(256) tree_gemm(int l) {
    constexpr int TILEM = 8 * TM;
    constexpr int NT = 19;
    int r = blockIdx.y;
    int li = l * 3 + r;
    int cnt = g_cnt[li];
    int row0 = blockIdx.x * TILEM;
    if (row0 >= cnt) return;
    const float* Wp = g_Wencp + (size_t)r * 300 * HSTR;

    __shared__ float As[2][TILEM][16];
    __shared__ float Ws[2][300][17];
    __shared__ int meta[TILEM];

    int tid = threadIdx.x, lane = tid & 31, warp = tid >> 5;
    if (tid < TILEM) {
        int rr = row0 + tid;
        meta[tid] = (rr < cnt) ? g_rows[li][rr] : -1;
    }
    __syncthreads();

    uint32_t asu[2] = { s2u(&As[0][0][0]), s2u(&As[1][0][0]) };
    uint32_t wsu[2] = { s2u(&Ws[0][0][0]), s2u(&Ws[1][0][0]) };

    // fill tile t into buffer buf
    auto fill = [&](int t, int buf) {
        int k0 = t * 16;
#pragma unroll
        for (int i = tid; i < TILEM * 16; i += 256) {
            int m = i >> 4, kk = i & 15;
            int mm = meta[m];
            const float* src = g_h + (mm < 0 ? 0 : (size_t)mm * HSTR) + k0 + kk;
            cpa4(asu[buf] + (uint32_t)((m * 16 + kk) << 2), src);
        }
        for (int i = tid; i < 300 * 16; i += 256) {
            int f = i >> 4, kk = i & 15;
            cpa4(wsu[buf] + (uint32_t)((f * 17 + kk) << 2), Wp + (size_t)f * HSTR + k0 + kk);
        }
        cpa_commit();
    };

    unsigned long long acc[TM][5];
#pragma unroll
    for (int i = 0; i < TM; i++)
#pragma unroll
        for (int j = 0; j < 5; j++) acc[i][j] = 0ull;

    fill(0, 0);
    for (int t = 0; t < NT; t++) {
        int buf = t & 1;
        if (t < NT - 1) { fill(t + 1, buf ^ 1); cpa_wait<1>(); }
        else            { cpa_wait<0>(); }
        __syncthreads();
#pragma unroll 4
        for (int kk = 0; kk < 16; kk++) {
            unsigned long long a2[TM];
#pragma unroll
            for (int i = 0; i < TM; i++) {
                float a = As[buf][warp * TM + i][kk];
                a2[i] = pk(a, a);
            }
            unsigned long long w2[5];
#pragma unroll
            for (int j = 0; j < 5; j++) {
                int f0 = lane + 64 * j;
                float wlo = Ws[buf][f0][kk];
                float whi = (f0 + 32 < EMB) ? Ws[buf][f0 + 32][kk] : 0.f;
                w2[j] = pk(wlo, whi);
            }
#pragma unroll
            for (int i = 0; i < TM; i++)
#pragma unroll
                for (int j = 0; j < 5; j++) ffma2(acc[i][j], a2[i], w2[j]);
        }
        __syncthreads();
    }

#pragma unroll
    for (int i = 0; i < TM; i++) {
        int mm = meta[warp * TM + i];
        if (mm < 0) continue;
        float* o = g_t + (size_t)mm * HSTR;
#pragma unroll
        for (int j = 0; j < 5; j++) {
            float lo, hi; upk(acc[i][j], lo, hi);
            int f0 = lane + 64 * j;
            o[f0] = lo;
            if (f0 + 32 < EMB) o[f0 + 32] = hi;
        }
    }
}

// ---------------- combine: one block per (parent, b, tree) ---------------------
__global__ void update_kernel(const int* __restrict__ prel, const int* __restrict__ hrel,
                              int plo) {
    int p = plo + blockIdx.x;
    int b = blockIdx.y, tree = blockIdx.z;
    int e = threadIdx.x;
    if (e >= EMB) return;
    const int* rel = (tree ? hrel : prel) + b * 64;
    float* hb = g_h + ((size_t)(tree * BATCH + b) * NNODE) * HSTR;
    const float* tb = g_t + ((size_t)(tree * BATCH + b) * NNODE) * HSTR;
    int c0 = 4 * p + 1;
    int c1 = 4 * p + 4; if (c1 > 63) c1 = 63;
    float s = 0.f;
#pragma unroll
    for (int c = c0; c <= c1; c++) {
        unsigned rid = (unsigned)rel[c];
        s += (rid <= 2u) ? tb[c * HSTR + e] : hb[c * HSTR + e];
    }
    float mean = s / (float)(c1 - c0 + 1);
    float v = hb[p * HSTR + e] * mean;
    hb[p * HSTR + e] = v > 0.f ? v : 0.f;
}

// ---------------- MLP input -----------------------------------------------------
__global__ void build_x_kernel() {
    int b = blockIdx.x;
    int e = threadIdx.x;
    float* x = g_x + (size_t)b * 1808;
    if (e >= EMB) { if (e < 308 && e >= 300) x[1500 + e] = 0.f; return; }  // pads 1800..1807
    float pr = g_rep[b * EMB + e];
    float hr = g_rep[(BATCH + b) * EMB + e];
    float ps = g_h[((size_t)b * NNODE) * HSTR + e];
    float hs = g_h[((size_t)(BATCH + b) * NNODE) * HSTR + e];
    x[e] = pr; x[300 + e] = hr; x[600 + e] = pr - hr; x[900 + e] = pr * hr;
    x[1200 + e] = ps - hs; x[1500 + e] = ps * hs;
}

// ---------------- MLP GEMM: 16 rows/block, double-buffered, k-split slabs -------
__global__ void __launch_bounds__(256) fc_gemm(int sel, int kpad, int ksl) {
    const float* A  = (sel == 0) ? g_x : (sel == 1) ? g_y0 : g_y1;
    const float* Wp = (sel == 0) ? g_W0p : (sel == 1) ? g_W12p : (g_W12p + 600 * 608);
    float* out = (sel == 0) ? g_acc0 : (sel == 1) ? g_acc1 : g_acc2;
    int m0 = blockIdx.x * 16;
    int fs = blockIdx.y * 300;
    int z = blockIdx.z;
    int kbeg = z * ksl;
    int kend = kbeg + ksl; if (kend > kpad) kend = kpad;
    int nt = (kend - kbeg) >> 4;

    __shared__ float As[2][16][16];
    __shared__ float Ws[2][300][17];
    int tid = threadIdx.x, lane = tid & 31, warp = tid >> 5;

    uint32_t asu[2] = { s2u(&As[0][0][0]), s2u(&As[1][0][0]) };
    uint32_t wsu[2] = { s2u(&Ws[0][0][0]), s2u(&Ws[1][0][0]) };

    auto fill = [&](int t, int buf) {
        int k0 = kbeg + t * 16;
        {
            int m = tid >> 4, kk = tid & 15;
            cpa4(asu[buf] + (uint32_t)(tid << 2), A + (size_t)(m0 + m) * kpad + k0 + kk);
        }
        for (int i = tid; i < 300 * 16; i += 256) {
            int f = i >> 4, kk = i & 15;
            cpa4(wsu[buf] + (uint32_t)((f * 17 + kk) << 2),
                 Wp + (size_t)(fs + f) * kpad + k0 + kk);
        }
        cpa_commit();
    };

    unsigned long long acc[2][5];
#pragma unroll
    for (int i = 0; i < 2; i++)
#pragma unroll
        for (int j = 0; j < 5; j++) acc[i][j] = 0ull;

    fill(0, 0);
    for (int t = 0; t < nt; t++) {
        int buf = t & 1;
        if (t < nt - 1) { fill(t + 1, buf ^ 1); cpa_wait<1>(); }
        else            { cpa_wait<0>(); }
        __syncthreads();
#pragma unroll 4
        for (int kk = 0; kk < 16; kk++) {
            unsigned long long a2[2];
#pragma unroll
            for (int i = 0; i < 2; i++) {
                float a = As[buf][warp * 2 + i][kk];
                a2[i] = pk(a, a);
            }
            unsigned long long w2[5];
#pragma unroll
            for (int j = 0; j < 5; j++) {
                int f0 = lane + 64 * j;
                float wlo = Ws[buf][f0][kk];
                float whi = (f0 + 32 < 300) ? Ws[buf][f0 + 32][kk] : 0.f;
                w2[j] = pk(wlo, whi);
            }
#pragma unroll
            for (int i = 0; i < 2; i++)
#pragma unroll
                for (int j = 0; j < 5; j++) ffma2(acc[i][j], a2[i], w2[j]);
        }
        __syncthreads();
    }

#pragma unroll
    for (int i = 0; i < 2; i++) {
        float* o = out + (size_t)z * BATCH * 600 + (size_t)(m0 + warp * 2 + i) * 600 + fs;
#pragma unroll
        for (int j = 0; j < 5; j++) {
            float lo, hi; upk(acc[i][j], lo, hi);
            int f0 = lane + 64 * j;
            o[f0] = lo;
            if (f0 + 32 < 300) o[f0 + 32] = hi;
        }
    }
}

// ---------------- reduce k-split slabs + bias + relu ----------------------------
__global__ void bias_relu_kernel(const float* __restrict__ bias, int sel, int nz) {
    int b = blockIdx.x, n = threadIdx.x;   // 608 threads
    float* y = (sel == 0) ? g_y0 : (sel == 1) ? g_y1 : g_y2;
    if (n >= 600) { y[b * 608 + n] = 0.f; return; }
    const float* acc = (sel == 0) ? g_acc0 : (sel == 1) ? g_acc1 : g_acc2;
    float s = bias[n];
    for (int z = 0; z < nz; z++) s += acc[(size_t)z * BATCH * 600 + b * 600 + n];
    y[b * 608 + n] = s > 0.f ? s : 0.f;
}

// ---------------- output layer ---------------------------------------------------
__global__ void out_kernel(const float* __restrict__ Wout, const float* __restrict__ bout,
                           float* __restrict__ out) {
    int b = blockIdx.x;
    int w = threadIdx.x >> 5, lane = threadIdx.x & 31;
    if (w >= 3) return;
    float s = 0.f;
    for (int k = lane; k < 600; k += 32)
        s += g_y2[b * 608 + k] * Wout[w * 600 + k];
    for (int o = 16; o; o >>= 1) s += __shfl_down_sync(0xffffffffu, s, o);
    if (lane == 0) out[b * 3 + w] = s + bout[w];
}

// ---------------- launch ----------------------------------------------------------
extern "C" void kernel_launch(void* const* d_in, const int* in_sizes, int n_in,
                              void* d_out, int out_size) {
    const int*   px   = (const int*)d_in[0];
    const int*   hx   = (const int*)d_in[1];
    const int*   pwi  = (const int*)d_in[2];
    const int*   prel = (const int*)d_in[3];
    const int*   hwi  = (const int*)d_in[4];
    const int*   hrel = (const int*)d_in[5];
    const float* E    = (const float*)d_in[8];
    const float* Wenc = (const float*)d_in[9];
    const float* W0w  = (const float*)d_in[10];
    const float* W0b  = (const float*)d_in[11];
    const float* W1w  = (const float*)d_in[12];
    const float* W1b  = (const float*)d_in[13];
    const float* W2w  = (const float*)d_in[14];
    const float* W2b  = (const float*)d_in[15];
    const float* Wow  = (const float*)d_in[16];
    const float* Wob  = (const float*)d_in[17];
    float* out = (float*)d_out;

    // launches 1-5 (so the profiler's 6th launch is the hot level-3 GEMM)
    pad_enc<<<900, 304>>>(Wenc);                          // 1
    rep_kernel<<<dim3(256, 2), 320>>>(px, hx, E);         // 2
    leaf_kernel<<<dim3(256, 2), 320>>>(px, hx, pwi, hwi, E); // 3
    compact_kernel<<<9, 1024>>>(prel, hrel);              // 4
    pad_w0<<<600, 512>>>(W0w);                            // 5

    // level 3
    tree_gemm<8><<<dim3(344, 3), 256>>>(2);               // 6  <- profiled
    update_kernel<<<dim3(11, 256, 2), 320>>>(prel, hrel, 5);
    pad_w12<<<1200, 608>>>(W1w, W2w);
    // level 2
    tree_gemm<4><<<dim3(256, 3), 256>>>(1);
    update_kernel<<<dim3(4, 256, 2), 320>>>(prel, hrel, 1);
    // level 1
    tree_gemm<1><<<dim3(256, 3), 256>>>(0);
    update_kernel<<<dim3(1, 256, 2), 320>>>(prel, hrel, 0);

    build_x_kernel<<<256, 320>>>();

    fc_gemm<<<dim3(16, 2, 5), 256>>>(0, 1808, 368);
    bias_relu_kernel<<<256, 608>>>(W0b, 0, 5);
    fc_gemm<<<dim3(16, 2, 2), 256>>>(1, 608, 304);
    bias_relu_kernel<<<256, 608>>>(W1b, 1, 2);
    fc_gemm<<<dim3(16, 2, 2), 256>>>(2, 608, 304);
    bias_relu_kernel<<<256, 608>>>(W2b, 2, 2);

    out_kernel<<<256, 96>>>(Wow, Wob, out);
}

// round 3
// speedup vs baseline: 2.4721x; 1.5611x over previous
#include <cuda_runtime.h>
#include <cstdint>

#define EMB 300
#define HSTR 304
#define BATCH 256
#define NNODE 64

// ---------------- scratch (static device memory; zero-initialized) -----------
__device__ float g_h[2 * BATCH * NNODE * HSTR];
__device__ float g_t[2 * BATCH * NNODE * HSTR];
__device__ float g_rep[2 * BATCH * EMB];
__device__ float g_x[BATCH * 1808];
__device__ float g_y0[BATCH * 608];
__device__ float g_y1[BATCH * 608];
__device__ float g_y2[BATCH * 608];
__device__ float g_acc0[10 * BATCH * 600];
__device__ float g_acc1[8 * BATCH * 600];
__device__ float g_acc2[8 * BATCH * 600];
// k-major, pair-permuted weights: [slice][k][320], pair p=(j*32+lane)*2+hi -> f=lane+64j+32hi
__device__ float g_WencT[3 * 304 * 320];
__device__ float g_W0T[2 * 1808 * 320];
__device__ float g_W12T[4 * 608 * 320];
__device__ int   g_rows[9][22016];
__device__ int   g_cnt[9];

// ---------------- helpers -----------------------------------------------------
__device__ __forceinline__ void upk(unsigned long long v, float& lo, float& hi) {
    asm("mov.b64 {%0,%1},%2;" : "=f"(lo), "=f"(hi) : "l"(v));
}
__device__ __forceinline__ void ffma2(unsigned long long& d, unsigned long long a,
                                      unsigned long long b) {
    asm("fma.rn.f32x2 %0,%1,%2,%0;" : "+l"(d) : "l"(a), "l"(b));
}
__device__ __forceinline__ uint32_t s2u(const void* p) {
    return (uint32_t)__cvta_generic_to_shared(p);
}
__device__ __forceinline__ void cpa4(uint32_t s, const float* g) {
    asm volatile("cp.async.ca.shared.global [%0],[%1],4;" :: "r"(s), "l"(g));
}
__device__ __forceinline__ void cpa16(uint32_t s, const float* g) {
    asm volatile("cp.async.cg.shared.global [%0],[%1],16;" :: "r"(s), "l"(g));
}
__device__ __forceinline__ void cpa_commit() { asm volatile("cp.async.commit_group;"); }
template <int N> __device__ __forceinline__ void cpa_wait() {
    asm volatile("cp.async.wait_group %0;" :: "n"(N));
}
__device__ __forceinline__ unsigned long long lds64(const float* p) {
    unsigned long long v;
    asm("ld.shared.b64 %0,[%1];" : "=l"(v) : "r"(s2u(p)));
    return v;
}

// ---------------- weight transpose+pair+pad ------------------------------------
// dst[slice][k][p], p in [0,320): q=p%64 within ftile j=p/64; w=(q>>1)+32*(q&1); f_local=64j+w
__global__ void wtrans_kernel(const float* __restrict__ srcA, const float* __restrict__ srcB,
                              int K, int Kpad, int zeroCnt) {
    float* dst = (K == 300) ? g_WencT : (K == 1800) ? g_W0T : g_W12T;
    int kt = blockIdx.x, j = blockIdx.y, sl = blockIdx.z;
    if (zeroCnt && kt == 0 && j == 0 && sl == 0 && threadIdx.x < 9) g_cnt[threadIdx.x] = 0;
    // source row pointer for slice
    const float* src;
    int fbase;
    if (K == 300)      { src = srcA + (size_t)sl * 300 * 300; fbase = 0; }
    else if (K == 1800){ src = srcA; fbase = sl * 300; }
    else               { src = (sl >= 2 ? srcB : srcA); fbase = (sl & 1) * 300; }
    __shared__ float s[64][17];
    int tid = threadIdx.x;
    int k0 = kt * 16;
#pragma unroll
    for (int pass = 0; pass < 4; pass++) {
        int fit = pass * 16 + (tid >> 4);     // f index within 64-tile
        int kk = tid & 15;
        int fl = j * 64 + fit;                // f_local within slice
        int k = k0 + kk;
        float v = 0.f;
        if (fl < 300 && k < K) v = src[(size_t)(fbase + fl) * K + k];
        s[fit][kk] = v;
    }
    __syncthreads();
#pragma unroll
    for (int pass = 0; pass < 4; pass++) {
        int kin = pass * 4 + (tid >> 6);
        int q = tid & 63;
        int w = (q >> 1) + ((q & 1) << 5);
        dst[((size_t)sl * Kpad + k0 + kin) * 320 + j * 64 + q] = s[w][kin];
    }
}

// ---------------- fused embeddings: rep sums + leaf word vectors ---------------
__global__ void embed_kernel(const int* __restrict__ px, const int* __restrict__ hx,
                             const int* __restrict__ pwi, const int* __restrict__ hwi,
                             const float* __restrict__ E) {
    int b = blockIdx.x, tree = blockIdx.y;
    const int* x  = (tree ? hx : px) + b * 64;
    const int* wi = (tree ? hwi : pwi) + b * 64;
    __shared__ int sx[64], swi[64];
    int tid = threadIdx.x;
    if (tid < 64) { sx[tid] = x[tid]; swi[tid] = wi[tid]; }
    __syncthreads();
    if (tid >= EMB) return;
    float rep = 0.f;
#pragma unroll 8
    for (int s = 0; s < 64; s++) rep += __ldg(&E[(size_t)sx[s] * EMB + tid]);
    g_rep[((size_t)tree * BATCH + b) * EMB + tid] = rep;
    float* hb = g_h + ((size_t)(tree * BATCH + b) * NNODE) * HSTR;
    for (int n = 0; n < 64; n++) {
        int w = swi[n];
        hb[n * HSTR + tid] = (w < 0) ? 1.0f : __ldg(&E[(size_t)sx[w] * EMB + tid]);
    }
}

// ---------------- parallel compaction per (level, rel) --------------------------
__global__ void compact_kernel(const int* __restrict__ prel, const int* __restrict__ hrel) {
    int li = blockIdx.y;
    int l = li / 3, r = li % 3;
    int n0, nc;
    if (l == 0)      { n0 = 1;  nc = 4;  }
    else if (l == 1) { n0 = 5;  nc = 16; }
    else             { n0 = 21; nc = 43; }
    int total = 512 * nc;
    int base = blockIdx.x * 2048;
    if (base >= total) return;
    __shared__ unsigned ball[64];
    __shared__ int pref[64];
    __shared__ int sbase;
    int tid = threadIdx.x, lane = tid & 31, wid = tid >> 5;
#pragma unroll
    for (int it = 0; it < 8; it++) {
        int i = base + it * 256 + tid;
        int flag = 0;
        if (i < total) {
            int tb = i / nc;
            int n = n0 + (i - tb * nc);
            int tree = tb >> 8, b = tb & 255;
            flag = ((tree ? hrel : prel)[b * 64 + n] == r);
        }
        unsigned m = __ballot_sync(0xffffffffu, flag);
        if (lane == 0) ball[wid * 8 + it] = m;
    }
    __syncthreads();
    if (tid == 0) {
        int run = 0;
        for (int s = 0; s < 64; s++) { pref[s] = run; run += __popc(ball[s]); }
        sbase = atomicAdd(&g_cnt[li], run);
    }
    __syncthreads();
#pragma unroll
    for (int it = 0; it < 8; it++) {
        int i = base + it * 256 + tid;
        int flag = 0, v = 0;
        if (i < total) {
            int tb = i / nc;
            int n = n0 + (i - tb * nc);
            int tree = tb >> 8, b = tb & 255;
            flag = ((tree ? hrel : prel)[b * 64 + n] == r);
            v = (tb << 6) | n;
        }
        unsigned m = ball[wid * 8 + it];
        int within = __popc(m & ((1u << lane) - 1));
        if (flag) g_rows[li][sbase + pref[wid * 8 + it] + within] = v;
    }
}

// ---------------- gathered GEMM: paired operands, double-buffered ---------------
template <int TM>
__global__ void __launch_bounds__(256) tree_gemm(int l) {
    constexpr int TILEM = 8 * TM;
    constexpr int NT = 19;
    int r = blockIdx.y;
    int li = l * 3 + r;
    int cnt = g_cnt[li];
    int row0 = blockIdx.x * TILEM;
    if (row0 >= cnt) return;
    const float* Wt = g_WencT + (size_t)r * 304 * 320;

    __shared__ float As2[2][TILEM][16][2];
    __shared__ float Ws[2][16][320];
    __shared__ int meta[TILEM];

    int tid = threadIdx.x, lane = tid & 31, warp = tid >> 5;
    if (tid < TILEM) {
        int rr = row0 + tid;
        meta[tid] = (rr < cnt) ? g_rows[li][rr] : -1;
    }
    __syncthreads();

    uint32_t asu[2] = { s2u(&As2[0][0][0][0]), s2u(&As2[1][0][0][0]) };
    uint32_t wsu[2] = { s2u(&Ws[0][0][0]), s2u(&Ws[1][0][0]) };

    auto fill = [&](int t, int buf) {
        int k0 = t * 16;
#pragma unroll
        for (int i = tid; i < TILEM * 16; i += 256) {
            int m = i >> 4, kk = i & 15;
            int mm = meta[m];
            const float* src = g_h + (mm < 0 ? 0 : (size_t)mm * HSTR) + k0 + kk;
            uint32_t d = asu[buf] + (uint32_t)(i << 3);
            cpa4(d, src); cpa4(d + 4, src);
        }
        const float* wsrc = Wt + (size_t)k0 * 320;
#pragma unroll
        for (int i = tid; i < 1280; i += 256)
            cpa16(wsu[buf] + (uint32_t)(i << 4), wsrc + (i << 2));
        cpa_commit();
    };

    unsigned long long acc[TM][5];
#pragma unroll
    for (int i = 0; i < TM; i++)
#pragma unroll
        for (int j = 0; j < 5; j++) acc[i][j] = 0ull;

    fill(0, 0);
    for (int t = 0; t < NT; t++) {
        int buf = t & 1;
        if (t < NT - 1) { fill(t + 1, buf ^ 1); cpa_wait<1>(); }
        else            { cpa_wait<0>(); }
        __syncthreads();
#pragma unroll
        for (int kk = 0; kk < 16; kk++) {
            unsigned long long w2[5];
#pragma unroll
            for (int j = 0; j < 5; j++)
                w2[j] = lds64(&Ws[buf][kk][(j * 32 + lane) * 2]);
#pragma unroll
            for (int i = 0; i < TM; i++) {
                unsigned long long a2 = lds64(&As2[buf][warp * TM + i][kk][0]);
#pragma unroll
                for (int j = 0; j < 5; j++) ffma2(acc[i][j], a2, w2[j]);
            }
        }
        __syncthreads();
    }

#pragma unroll
    for (int i = 0; i < TM; i++) {
        int mm = meta[warp * TM + i];
        if (mm < 0) continue;
        float* o = g_t + (size_t)mm * HSTR;
#pragma unroll
        for (int j = 0; j < 5; j++) {
            float lo, hi; upk(acc[i][j], lo, hi);
            int f0 = lane + 64 * j;
            o[f0] = lo;
            if (f0 + 32 < EMB) o[f0 + 32] = hi;
        }
    }
}

// ---------------- combine: h[p] = relu(h[p] * mean(children)) -------------------
__global__ void update_kernel(const int* __restrict__ prel, const int* __restrict__ hrel,
                              int plo) {
    int p = plo + blockIdx.x;
    int b = blockIdx.y, tree = blockIdx.z;
    int e = threadIdx.x;
    if (e >= EMB) return;
    const int* rel = (tree ? hrel : prel) + b * 64;
    float* hb = g_h + ((size_t)(tree * BATCH + b) * NNODE) * HSTR;
    const float* tb = g_t + ((size_t)(tree * BATCH + b) * NNODE) * HSTR;
    int c0 = 4 * p + 1;
    int c1 = 4 * p + 4; if (c1 > 63) c1 = 63;
    float s = 0.f;
#pragma unroll
    for (int c = c0; c <= c1; c++) {
        if (c > 63) break;
        unsigned rid = (unsigned)rel[c];
        s += (rid <= 2u) ? tb[c * HSTR + e] : hb[c * HSTR + e];
    }
    float mean = s / (float)(c1 - c0 + 1);
    float v = hb[p * HSTR + e] * mean;
    hb[p * HSTR + e] = v > 0.f ? v : 0.f;
}

// ---------------- MLP input ------------------------------------------------------
__global__ void build_x_kernel() {
    int b = blockIdx.x;
    int e = threadIdx.x;
    if (e >= EMB) return;
    float pr = g_rep[b * EMB + e];
    float hr = g_rep[(BATCH + b) * EMB + e];
    float ps = g_h[((size_t)b * NNODE) * HSTR + e];
    float hs = g_h[((size_t)(BATCH + b) * NNODE) * HSTR + e];
    float* x = g_x + (size_t)b * 1808;
    x[e] = pr; x[300 + e] = hr; x[600 + e] = pr - hr; x[900 + e] = pr * hr;
    x[1200 + e] = ps - hs; x[1500 + e] = ps * hs;
}

// ---------------- MLP GEMM: 32 rows/block, paired, double-buffered, k-split -----
__global__ void __launch_bounds__(256) fc_gemm(int sel, int kpad, int ksl) {
    const float* A  = (sel == 0) ? g_x : (sel == 1) ? g_y0 : g_y1;
    const float* Wt = (sel == 0) ? g_W0T : (sel == 1) ? g_W12T : (g_W12T + 2 * 608 * 320);
    float* out = (sel == 0) ? g_acc0 : (sel == 1) ? g_acc1 : g_acc2;
    int m0 = blockIdx.x * 32;
    int fs2 = blockIdx.y;
    int z = blockIdx.z;
    int kbeg = z * ksl;
    int kend = kbeg + ksl; if (kend > kpad) kend = kpad;
    int nt = (kend - kbeg) >> 4;
    const float* Wsl = Wt + (size_t)fs2 * kpad * 320;

    __shared__ float As2[2][32][16][2];
    __shared__ float Ws[2][16][320];
    int tid = threadIdx.x, lane = tid & 31, warp = tid >> 5;

    uint32_t asu[2] = { s2u(&As2[0][0][0][0]), s2u(&As2[1][0][0][0]) };
    uint32_t wsu[2] = { s2u(&Ws[0][0][0]), s2u(&Ws[1][0][0]) };

    auto fill = [&](int t, int buf) {
        int k0 = kbeg + t * 16;
#pragma unroll
        for (int i = tid; i < 512; i += 256) {
            int m = i >> 4, kk = i & 15;
            const float* src = A + (size_t)(m0 + m) * kpad + k0 + kk;
            uint32_t d = asu[buf] + (uint32_t)(i << 3);
            cpa4(d, src); cpa4(d + 4, src);
        }
        const float* wsrc = Wsl + (size_t)k0 * 320;
#pragma unroll
        for (int i = tid; i < 1280; i += 256)
            cpa16(wsu[buf] + (uint32_t)(i << 4), wsrc + (i << 2));
        cpa_commit();
    };

    unsigned long long acc[4][5];
#pragma unroll
    for (int i = 0; i < 4; i++)
#pragma unroll
        for (int j = 0; j < 5; j++) acc[i][j] = 0ull;

    fill(0, 0);
    for (int t = 0; t < nt; t++) {
        int buf = t & 1;
        if (t < nt - 1) { fill(t + 1, buf ^ 1); cpa_wait<1>(); }
        else            { cpa_wait<0>(); }
        __syncthreads();
#pragma unroll
        for (int kk = 0; kk < 16; kk++) {
            unsigned long long w2[5];
#pragma unroll
            for (int j = 0; j < 5; j++)
                w2[j] = lds64(&Ws[buf][kk][(j * 32 + lane) * 2]);
#pragma unroll
            for (int i = 0; i < 4; i++) {
                unsigned long long a2 = lds64(&As2[buf][warp * 4 + i][kk][0]);
#pragma unroll
                for (int j = 0; j < 5; j++) ffma2(acc[i][j], a2, w2[j]);
            }
        }
        __syncthreads();
    }

#pragma unroll
    for (int i = 0; i < 4; i++) {
        float* o = out + (size_t)z * BATCH * 600 + (size_t)(m0 + warp * 4 + i) * 600 + fs2 * 300;
#pragma unroll
        for (int j = 0; j < 5; j++) {
            float lo, hi; upk(acc[i][j], lo, hi);
            int f0 = lane + 64 * j;
            o[f0] = lo;
            if (f0 + 32 < 300) o[f0 + 32] = hi;
        }
    }
}

// ---------------- reduce k-split slabs + bias + relu -----------------------------
__global__ void bias_relu_kernel(const float* __restrict__ bias, int sel, int nz) {
    int b = blockIdx.x, n = threadIdx.x;   // 600 threads
    const float* acc = (sel == 0) ? g_acc0 : (sel == 1) ? g_acc1 : g_acc2;
    float s = bias[n];
    for (int z = 0; z < nz; z++) s += acc[(size_t)z * BATCH * 600 + b * 600 + n];
    float* y = (sel == 0) ? g_y0 : (sel == 1) ? g_y1 : g_y2;
    y[b * 608 + n] = s > 0.f ? s : 0.f;
}

// ---------------- output layer -----------------------------------------------------
__global__ void out_kernel(const float* __restrict__ Wout, const float* __restrict__ bout,
                           float* __restrict__ out) {
    int b = blockIdx.x;
    int w = threadIdx.x >> 5, lane = threadIdx.x & 31;
    if (w >= 3) return;
    float s = 0.f;
    for (int k = lane; k < 600; k += 32)
        s += g_y2[b * 608 + k] * Wout[w * 600 + k];
    for (int o = 16; o; o >>= 1) s += __shfl_down_sync(0xffffffffu, s, o);
    if (lane == 0) out[b * 3 + w] = s + bout[w];
}

// ---------------- launch ------------------------------------------------------------
extern "C" void kernel_launch(void* const* d_in, const int* in_sizes, int n_in,
                              void* d_out, int out_size) {
    const int*   px   = (const int*)d_in[0];
    const int*   hx   = (const int*)d_in[1];
    const int*   pwi  = (const int*)d_in[2];
    const int*   prel = (const int*)d_in[3];
    const int*   hwi  = (const int*)d_in[4];
    const int*   hrel = (const int*)d_in[5];
    const float* E    = (const float*)d_in[8];
    const float* Wenc = (const float*)d_in[9];
    const float* W0w  = (const float*)d_in[10];
    const float* W0b  = (const float*)d_in[11];
    const float* W1w  = (const float*)d_in[12];
    const float* W1b  = (const float*)d_in[13];
    const float* W2w  = (const float*)d_in[14];
    const float* W2b  = (const float*)d_in[15];
    const float* Wow  = (const float*)d_in[16];
    const float* Wob  = (const float*)d_in[17];
    float* out = (float*)d_out;

    // launches 1-5
    wtrans_kernel<<<dim3(19, 5, 3), 256>>>(Wenc, nullptr, 300, 304, 1);   // 1 (+zero g_cnt)
    embed_kernel<<<dim3(256, 2), 320>>>(px, hx, pwi, hwi, E);             // 2
    compact_kernel<<<dim3(11, 9), 256>>>(prel, hrel);                     // 3
    wtrans_kernel<<<dim3(113, 5, 2), 256>>>(W0w, nullptr, 1800, 1808, 0); // 4
    wtrans_kernel<<<dim3(38, 5, 4), 256>>>(W1w, W2w, 600, 608, 0);        // 5

    // level 3 (TILEM=96)                                                 // 6 <- profiled
    tree_gemm<12><<<dim3(230, 3), 256>>>(2);
    update_kernel<<<dim3(11, 256, 2), 320>>>(prel, hrel, 5);
    // level 2 (TILEM=40)
    tree_gemm<5><<<dim3(205, 3), 256>>>(1);
    update_kernel<<<dim3(4, 256, 2), 320>>>(prel, hrel, 1);
    // level 1 (TILEM=16)
    tree_gemm<2><<<dim3(128, 3), 256>>>(0);
    update_kernel<<<dim3(1, 256, 2), 320>>>(prel, hrel, 0);

    build_x_kernel<<<256, 320>>>();

    fc_gemm<<<dim3(8, 2, 10), 256>>>(0, 1808, 192);
    bias_relu_kernel<<<256, 600>>>(W0b, 0, 10);
    fc_gemm<<<dim3(8, 2, 8), 256>>>(1, 608, 80);
    bias_relu_kernel<<<256, 600>>>(W1b, 1, 8);
    fc_gemm<<<dim3(8, 2, 8), 256>>>(2, 608, 80);
    bias_relu_kernel<<<256, 600>>>(W2b, 2, 8);

    out_kernel<<<256, 96>>>(Wow, Wob, out);
}

// round 4
// speedup vs baseline: 2.6636x; 1.0775x over previous
#include <cuda_runtime.h>
#include <cstdint>

#define EMB 300
#define HSTR 304
#define BATCH 256
#define NNODE 64

// ---------------- scratch (static device memory; zero-initialized) -----------
__device__ float g_h[2 * BATCH * NNODE * HSTR];
__device__ float g_t[2 * BATCH * NNODE * HSTR];
__device__ float g_rep[2 * BATCH * EMB];
__device__ float g_x[BATCH * 1808];
__device__ float g_y0[BATCH * 608];
__device__ float g_y1[BATCH * 608];
__device__ float g_acc0[10 * BATCH * 600];
__device__ float g_acc1[8 * BATCH * 600];
__device__ float g_acc2[8 * BATCH * 600];
// k-major, pair-permuted weights: [slice][k][320], pair p=(j*32+lane)*2+hi -> f=lane+64j+32hi
__device__ float g_WencT[3 * 304 * 320];
__device__ float g_W0T[2 * 1808 * 320];
__device__ float g_W12T[4 * 608 * 320];
__device__ int   g_rows[9][22016];
__device__ int   g_cnt[9];

// ---------------- helpers -----------------------------------------------------
__device__ __forceinline__ void upk(unsigned long long v, float& lo, float& hi) {
    asm("mov.b64 {%0,%1},%2;" : "=f"(lo), "=f"(hi) : "l"(v));
}
__device__ __forceinline__ void ffma2(unsigned long long& d, unsigned long long a,
                                      unsigned long long b) {
    asm("fma.rn.f32x2 %0,%1,%2,%0;" : "+l"(d) : "l"(a), "l"(b));
}
__device__ __forceinline__ uint32_t s2u(const void* p) {
    return (uint32_t)__cvta_generic_to_shared(p);
}
__device__ __forceinline__ void cpa4(uint32_t s, const float* g) {
    asm volatile("cp.async.ca.shared.global [%0],[%1],4;" :: "r"(s), "l"(g));
}
__device__ __forceinline__ void cpa16(uint32_t s, const float* g) {
    asm volatile("cp.async.cg.shared.global [%0],[%1],16;" :: "r"(s), "l"(g));
}
__device__ __forceinline__ void cpa_commit() { asm volatile("cp.async.commit_group;"); }
template <int N> __device__ __forceinline__ void cpa_wait() {
    asm volatile("cp.async.wait_group %0;" :: "n"(N));
}
__device__ __forceinline__ unsigned long long lds64(const float* p) {
    unsigned long long v;
    asm("ld.shared.b64 %0,[%1];" : "=l"(v) : "r"(s2u(p)));
    return v;
}

// ---------------- 1. unified weight transpose+pair+pad -------------------------
// z: 0-2 Wenc slices, 3-4 W0 halves, 5-8 W1/W2 halves
__global__ void wtrans_all(const float* __restrict__ Wenc, const float* __restrict__ W0,
                           const float* __restrict__ W1, const float* __restrict__ W2) {
    int kt = blockIdx.x, j = blockIdx.y, z = blockIdx.z;
    int tid = threadIdx.x;
    if (z == 0 && kt == 0 && j == 0 && tid < 9) g_cnt[tid] = 0;
    const float* src; float* dst; int K, Kpad, fbase, sl;
    if (z < 3)      { K = 300;  Kpad = 304;  sl = z;     src = Wenc + (size_t)z * 300 * 300;
                      fbase = 0;            dst = g_WencT; if (kt >= 19)  return; }
    else if (z < 5) { K = 1800; Kpad = 1808; sl = z - 3; src = W0;
                      fbase = sl * 300;     dst = g_W0T;   if (kt >= 113) return; }
    else            { K = 600;  Kpad = 608;  sl = z - 5; src = (z >= 7) ? W2 : W1;
                      fbase = (sl & 1) * 300; dst = g_W12T; if (kt >= 38) return; }
    __shared__ float s[64][17];
    int k0 = kt * 16;
#pragma unroll
    for (int pass = 0; pass < 4; pass++) {
        int fit = pass * 16 + (tid >> 4);
        int kk = tid & 15;
        int fl = j * 64 + fit;
        int k = k0 + kk;
        float v = 0.f;
        if (fl < 300 && k < K) v = src[(size_t)(fbase + fl) * K + k];
        s[fit][kk] = v;
    }
    __syncthreads();
#pragma unroll
    for (int pass = 0; pass < 4; pass++) {
        int kin = pass * 4 + (tid >> 6);
        int q = tid & 63;
        int w = (q >> 1) + ((q & 1) << 5);
        dst[((size_t)sl * Kpad + k0 + kin) * 320 + j * 64 + q] = s[w][kin];
    }
}

// ---------------- 2. prep: embeddings (blocks 0-511) + compaction (512-610) ----
__global__ void prep_kernel(const int* __restrict__ px, const int* __restrict__ hx,
                            const int* __restrict__ pwi, const int* __restrict__ hwi,
                            const float* __restrict__ E,
                            const int* __restrict__ prel, const int* __restrict__ hrel) {
    __shared__ int sx[64], swi[64];
    __shared__ unsigned ball[64];
    __shared__ int pref[64];
    __shared__ int sbase;
    int tid = threadIdx.x, lane = tid & 31, wid = tid >> 5;

    if (blockIdx.x < 512) {
        // ---- embed path ----
        int b = blockIdx.x & 255, tree = blockIdx.x >> 8;
        const int* x  = (tree ? hx : px) + b * 64;
        const int* wi = (tree ? hwi : pwi) + b * 64;
        if (tid < 64) { sx[tid] = x[tid]; swi[tid] = wi[tid]; }
        __syncthreads();
        if (tid >= 304) return;
        float* hb = g_h + ((size_t)(tree * BATCH + b) * NNODE) * HSTR;
        if (tid >= 300) {          // keep pad columns zero
            for (int n = 0; n < 64; n++) hb[n * HSTR + tid] = 0.f;
            return;
        }
        float rep = 0.f;
#pragma unroll 8
        for (int s = 0; s < 64; s++) rep += __ldg(&E[(size_t)sx[s] * EMB + tid]);
        g_rep[((size_t)tree * BATCH + b) * EMB + tid] = rep;
        for (int n = 0; n < 64; n++) {
            int w = swi[n];
            hb[n * HSTR + tid] = (w < 0) ? 1.0f : __ldg(&E[(size_t)sx[w] * EMB + tid]);
        }
        return;
    }

    // ---- compact path ----
    int cb = blockIdx.x - 512;
    int li = cb % 9, chunk = cb / 9;
    int l = li / 3, r = li % 3;
    int n0, nc;
    if (l == 0)      { n0 = 1;  nc = 4;  }
    else if (l == 1) { n0 = 5;  nc = 16; }
    else             { n0 = 21; nc = 43; }
    int total = 512 * nc;
    int base = chunk * 2048;
    if (base >= total) return;
    if (tid < 256) {
#pragma unroll
        for (int it = 0; it < 8; it++) {
            int i = base + it * 256 + tid;
            int flag = 0;
            if (i < total) {
                int tb = i / nc;
                int n = n0 + (i - tb * nc);
                int tree = tb >> 8, b = tb & 255;
                flag = ((tree ? hrel : prel)[b * 64 + n] == r);
            }
            unsigned m = __ballot_sync(0xffffffffu, flag);
            if (lane == 0) ball[wid * 8 + it] = m;
        }
    }
    __syncthreads();
    if (tid == 0) {
        int run = 0;
        for (int s = 0; s < 64; s++) { pref[s] = run; run += __popc(ball[s]); }
        sbase = atomicAdd(&g_cnt[li], run);
    }
    __syncthreads();
    if (tid < 256) {
#pragma unroll
        for (int it = 0; it < 8; it++) {
            int i = base + it * 256 + tid;
            int flag = 0, v = 0;
            if (i < total) {
                int tb = i / nc;
                int n = n0 + (i - tb * nc);
                int tree = tb >> 8, b = tb & 255;
                flag = ((tree ? hrel : prel)[b * 64 + n] == r);
                v = (tb << 6) | n;
            }
            unsigned m = ball[wid * 8 + it];
            int within = __popc(m & ((1u << lane) - 1));
            if (flag) g_rows[li][sbase + pref[wid * 8 + it] + within] = v;
        }
    }
}

// ---------------- 3. gathered GEMM: paired operands, double-buffered ------------
template <int TM>
__global__ void __launch_bounds__(256) tree_gemm(int l) {
    constexpr int TILEM = 8 * TM;
    constexpr int NT = 19;
    int r = blockIdx.y;
    int li = l * 3 + r;
    int cnt = g_cnt[li];
    int row0 = blockIdx.x * TILEM;
    if (row0 >= cnt) return;
    const float* Wt = g_WencT + (size_t)r * 304 * 320;

    __shared__ float As2[2][TILEM][16][2];
    __shared__ float Ws[2][16][320];
    __shared__ int meta[TILEM];

    int tid = threadIdx.x, lane = tid & 31, warp = tid >> 5;
    if (tid < TILEM) {
        int rr = row0 + tid;
        meta[tid] = (rr < cnt) ? g_rows[li][rr] : -1;
    }
    __syncthreads();

    uint32_t asu[2] = { s2u(&As2[0][0][0][0]), s2u(&As2[1][0][0][0]) };
    uint32_t wsu[2] = { s2u(&Ws[0][0][0]), s2u(&Ws[1][0][0]) };

    auto fill = [&](int t, int buf) {
        int k0 = t * 16;
#pragma unroll
        for (int i = tid; i < TILEM * 16; i += 256) {
            int m = i >> 4, kk = i & 15;
            int mm = meta[m];
            const float* src = g_h + (mm < 0 ? 0 : (size_t)mm * HSTR) + k0 + kk;
            uint32_t d = asu[buf] + (uint32_t)(i << 3);
            cpa4(d, src); cpa4(d + 4, src);
        }
        const float* wsrc = Wt + (size_t)k0 * 320;
#pragma unroll
        for (int i = tid; i < 1280; i += 256)
            cpa16(wsu[buf] + (uint32_t)(i << 4), wsrc + (i << 2));
        cpa_commit();
    };

    unsigned long long acc[TM][5];
#pragma unroll
    for (int i = 0; i < TM; i++)
#pragma unroll
        for (int j = 0; j < 5; j++) acc[i][j] = 0ull;

    fill(0, 0);
    for (int t = 0; t < NT; t++) {
        int buf = t & 1;
        if (t < NT - 1) { fill(t + 1, buf ^ 1); cpa_wait<1>(); }
        else            { cpa_wait<0>(); }
        __syncthreads();
#pragma unroll
        for (int kk = 0; kk < 16; kk++) {
            unsigned long long w2[5];
#pragma unroll
            for (int j = 0; j < 5; j++)
                w2[j] = lds64(&Ws[buf][kk][(j * 32 + lane) * 2]);
#pragma unroll
            for (int i = 0; i < TM; i++) {
                unsigned long long a2 = lds64(&As2[buf][warp * TM + i][kk][0]);
#pragma unroll
                for (int j = 0; j < 5; j++) ffma2(acc[i][j], a2, w2[j]);
            }
        }
        __syncthreads();
    }

#pragma unroll
    for (int i = 0; i < TM; i++) {
        int mm = meta[warp * TM + i];
        if (mm < 0) continue;
        float* o = g_t + (size_t)mm * HSTR;
#pragma unroll
        for (int j = 0; j < 5; j++) {
            float lo, hi; upk(acc[i][j], lo, hi);
            int f0 = lane + 64 * j;
            o[f0] = lo;
            if (f0 + 32 < EMB) o[f0 + 32] = hi;
        }
    }
}

// ---------------- 4. combine (float4): h[p] = relu(h[p] * mean(children)) ------
__global__ void update_kernel(const int* __restrict__ prel, const int* __restrict__ hrel,
                              int plo) {
    int p = plo + blockIdx.x;
    int b = blockIdx.y, tree = blockIdx.z;
    int e4 = threadIdx.x;
    if (e4 >= 76) return;
    const int* rel = (tree ? hrel : prel) + b * 64;
    size_t base = ((size_t)(tree * BATCH + b) * NNODE) * HSTR;
    const float4* hb = (const float4*)(g_h + base);
    const float4* tb = (const float4*)(g_t + base);
    int c0 = 4 * p + 1;
    int c1 = 4 * p + 4; if (c1 > 63) c1 = 63;
    float4 s = make_float4(0.f, 0.f, 0.f, 0.f);
#pragma unroll
    for (int c = c0; c <= c1; c++) {
        if (c > 63) break;
        unsigned rid = (unsigned)rel[c];
        const float4* src = (rid <= 2u) ? tb : hb;
        float4 v = src[c * 76 + e4];
        s.x += v.x; s.y += v.y; s.z += v.z; s.w += v.w;
    }
    float cntf = (float)(c1 - c0 + 1);
    float4 hp = hb[p * 76 + e4];
    float4 o;
    o.x = fmaxf(hp.x * (s.x / cntf), 0.f);
    o.y = fmaxf(hp.y * (s.y / cntf), 0.f);
    o.z = fmaxf(hp.z * (s.z / cntf), 0.f);
    o.w = fmaxf(hp.w * (s.w / cntf), 0.f);
    ((float4*)(g_h + base))[p * 76 + e4] = o;
}

// ---------------- 5. fused root update (level 1) + MLP input build -------------
__global__ void update1_buildx(const int* __restrict__ prel, const int* __restrict__ hrel) {
    int b = blockIdx.x;
    int e = threadIdx.x;        // 320 threads, 300 active
    __shared__ float root[2][300];
#pragma unroll
    for (int tree = 0; tree < 2; tree++) {
        if (e < 300) {
            const int* rel = (tree ? hrel : prel) + b * 64;
            size_t base = ((size_t)(tree * BATCH + b) * NNODE) * HSTR;
            const float* hb = g_h + base;
            const float* tb = g_t + base;
            float s = 0.f;
#pragma unroll
            for (int c = 1; c <= 4; c++) {
                unsigned rid = (unsigned)rel[c];
                s += (rid <= 2u) ? tb[c * HSTR + e] : hb[c * HSTR + e];
            }
            float v = hb[e] * (s * 0.25f);
            root[tree][e] = fmaxf(v, 0.f);
        }
    }
    __syncthreads();
    if (e >= 300) return;
    float pr = g_rep[b * EMB + e];
    float hr = g_rep[(BATCH + b) * EMB + e];
    float ps = root[0][e], hs = root[1][e];
    float* x = g_x + (size_t)b * 1808;
    x[e] = pr; x[300 + e] = hr; x[600 + e] = pr - hr; x[900 + e] = pr * hr;
    x[1200 + e] = ps - hs; x[1500 + e] = ps * hs;
}

// ---------------- 6. MLP GEMM: 32 rows/block, paired, double-buffered, k-split --
__global__ void __launch_bounds__(256) fc_gemm(int sel, int kpad, int ksl) {
    const float* A  = (sel == 0) ? g_x : (sel == 1) ? g_y0 : g_y1;
    const float* Wt = (sel == 0) ? g_W0T : (sel == 1) ? g_W12T : (g_W12T + 2 * 608 * 320);
    float* out = (sel == 0) ? g_acc0 : (sel == 1) ? g_acc1 : g_acc2;
    int m0 = blockIdx.x * 32;
    int fs2 = blockIdx.y;
    int z = blockIdx.z;
    int kbeg = z * ksl;
    int kend = kbeg + ksl; if (kend > kpad) kend = kpad;
    int nt = (kend - kbeg) >> 4;
    const float* Wsl = Wt + (size_t)fs2 * kpad * 320;

    __shared__ float As2[2][32][16][2];
    __shared__ float Ws[2][16][320];
    int tid = threadIdx.x, lane = tid & 31, warp = tid >> 5;

    uint32_t asu[2] = { s2u(&As2[0][0][0][0]), s2u(&As2[1][0][0][0]) };
    uint32_t wsu[2] = { s2u(&Ws[0][0][0]), s2u(&Ws[1][0][0]) };

    auto fill = [&](int t, int buf) {
        int k0 = kbeg + t * 16;
#pragma unroll
        for (int i = tid; i < 512; i += 256) {
            int m = i >> 4, kk = i & 15;
            const float* src = A + (size_t)(m0 + m) * kpad + k0 + kk;
            uint32_t d = asu[buf] + (uint32_t)(i << 3);
            cpa4(d, src); cpa4(d + 4, src);
        }
        const float* wsrc = Wsl + (size_t)k0 * 320;
#pragma unroll
        for (int i = tid; i < 1280; i += 256)
            cpa16(wsu[buf] + (uint32_t)(i << 4), wsrc + (i << 2));
        cpa_commit();
    };

    unsigned long long acc[4][5];
#pragma unroll
    for (int i = 0; i < 4; i++)
#pragma unroll
        for (int j = 0; j < 5; j++) acc[i][j] = 0ull;

    fill(0, 0);
    for (int t = 0; t < nt; t++) {
        int buf = t & 1;
        if (t < nt - 1) { fill(t + 1, buf ^ 1); cpa_wait<1>(); }
        else            { cpa_wait<0>(); }
        __syncthreads();
#pragma unroll
        for (int kk = 0; kk < 16; kk++) {
            unsigned long long w2[5];
#pragma unroll
            for (int j = 0; j < 5; j++)
                w2[j] = lds64(&Ws[buf][kk][(j * 32 + lane) * 2]);
#pragma unroll
            for (int i = 0; i < 4; i++) {
                unsigned long long a2 = lds64(&As2[buf][warp * 4 + i][kk][0]);
#pragma unroll
                for (int j = 0; j < 5; j++) ffma2(acc[i][j], a2, w2[j]);
            }
        }
        __syncthreads();
    }

#pragma unroll
    for (int i = 0; i < 4; i++) {
        float* o = out + (size_t)z * BATCH * 600 + (size_t)(m0 + warp * 4 + i) * 600 + fs2 * 300;
#pragma unroll
        for (int j = 0; j < 5; j++) {
            float lo, hi; upk(acc[i][j], lo, hi);
            int f0 = lane + 64 * j;
            o[f0] = lo;
            if (f0 + 32 < 300) o[f0 + 32] = hi;
        }
    }
}

// ---------------- 7. reduce k-split slabs + bias + relu -------------------------
__global__ void bias_relu_kernel(const float* __restrict__ bias, int sel, int nz) {
    int b = blockIdx.x, n = threadIdx.x;   // 600 threads
    const float* acc = (sel == 0) ? g_acc0 : g_acc1;
    float s = bias[n];
    for (int z = 0; z < nz; z++) s += acc[(size_t)z * BATCH * 600 + b * 600 + n];
    float* y = (sel == 0) ? g_y0 : g_y1;
    y[b * 608 + n] = s > 0.f ? s : 0.f;
}

// ---------------- 8. fused layer-2 reduce + bias + relu + output ----------------
__global__ void bias2_out(const float* __restrict__ bias, const float* __restrict__ Wout,
                          const float* __restrict__ bout, float* __restrict__ out) {
    int b = blockIdx.x, n = threadIdx.x;   // 608 threads
    __shared__ float sy[600];
    if (n < 600) {
        float s = bias[n];
        for (int z = 0; z < 8; z++) s += g_acc2[(size_t)z * BATCH * 600 + b * 600 + n];
        sy[n] = s > 0.f ? s : 0.f;
    }
    __syncthreads();
    int w = n >> 5, lane = n & 31;
    if (w >= 3) return;
    float s = 0.f;
    for (int k = lane; k < 600; k += 32)
        s += sy[k] * Wout[w * 600 + k];
    for (int o = 16; o; o >>= 1) s += __shfl_down_sync(0xffffffffu, s, o);
    if (lane == 0) out[b * 3 + w] = s + bout[w];
}

// ---------------- launch ----------------------------------------------------------
extern "C" void kernel_launch(void* const* d_in, const int* in_sizes, int n_in,
                              void* d_out, int out_size) {
    const int*   px   = (const int*)d_in[0];
    const int*   hx   = (const int*)d_in[1];
    const int*   pwi  = (const int*)d_in[2];
    const int*   prel = (const int*)d_in[3];
    const int*   hwi  = (const int*)d_in[4];
    const int*   hrel = (const int*)d_in[5];
    const float* E    = (const float*)d_in[8];
    const float* Wenc = (const float*)d_in[9];
    const float* W0w  = (const float*)d_in[10];
    const float* W0b  = (const float*)d_in[11];
    const float* W1w  = (const float*)d_in[12];
    const float* W1b  = (const float*)d_in[13];
    const float* W2w  = (const float*)d_in[14];
    const float* W2b  = (const float*)d_in[15];
    const float* Wow  = (const float*)d_in[16];
    const float* Wob  = (const float*)d_in[17];
    float* out = (float*)d_out;

    wtrans_all<<<dim3(113, 5, 9), 256>>>(Wenc, W0w, W1w, W2w);            // 1
    prep_kernel<<<611, 320>>>(px, hx, pwi, hwi, E, prel, hrel);           // 2

    tree_gemm<12><<<dim3(230, 3), 256>>>(2);                              // 3
    update_kernel<<<dim3(11, 256, 2), 96>>>(prel, hrel, 5);               // 4
    tree_gemm<5><<<dim3(205, 3), 256>>>(1);                               // 5
    update_kernel<<<dim3(4, 256, 2), 96>>>(prel, hrel, 1);                // 6
    tree_gemm<2><<<dim3(128, 3), 256>>>(0);                               // 7
    update1_buildx<<<256, 320>>>(prel, hrel);                             // 8

    fc_gemm<<<dim3(8, 2, 10), 256>>>(0, 1808, 192);                       // 9
    bias_relu_kernel<<<256, 600>>>(W0b, 0, 10);                           // 10
    fc_gemm<<<dim3(8, 2, 8), 256>>>(1, 608, 80);                          // 11
    bias_relu_kernel<<<256, 600>>>(W1b, 1, 8);                            // 12
    fc_gemm<<<dim3(8, 2, 8), 256>>>(2, 608, 80);                          // 13
    bias2_out<<<256, 608>>>(W2b, Wow, Wob, out);                          // 14
}

// round 6
// speedup vs baseline: 3.0847x; 1.1581x over previous
#include <cuda_runtime.h>
#include <cuda_bf16.h>
#include <cstdint>

#define EMB 300
#define HSTR 304
#define BATCH 256
#define NNODE 64

// ---------------- scratch (static device memory; zero-initialized) -----------
__device__ float g_h[2 * BATCH * NNODE * HSTR];
__device__ float g_t[2 * BATCH * NNODE * HSTR];
__device__ __align__(16) __nv_bfloat16 g_hbhi[2 * BATCH * NNODE * 320];
__device__ __align__(16) __nv_bfloat16 g_hblo[2 * BATCH * NNODE * 320];
__device__ __align__(16) __nv_bfloat16 g_WencK[3 * 2 * 320 * 320]; // [rel][hi/lo][f][k]
__device__ __align__(16) float g_zero[8];                          // stays zero
__device__ float g_rep[2 * BATCH * EMB];
__device__ float g_x[BATCH * 1808];
__device__ float g_y0[BATCH * 608];
__device__ float g_y1[BATCH * 608];
__device__ float g_acc0[10 * BATCH * 600];
__device__ float g_acc1[8 * BATCH * 600];
__device__ float g_acc2[8 * BATCH * 600];
__device__ float g_W0T[2 * 1808 * 320];
__device__ float g_W12T[4 * 608 * 320];
__device__ int   g_rows[9][22016];
__device__ int   g_cnt[9];

// ---------------- helpers -----------------------------------------------------
__device__ __forceinline__ void upk(unsigned long long v, float& lo, float& hi) {
    asm("mov.b64 {%0,%1},%2;" : "=f"(lo), "=f"(hi) : "l"(v));
}
__device__ __forceinline__ void ffma2(unsigned long long& d, unsigned long long a,
                                      unsigned long long b) {
    asm("fma.rn.f32x2 %0,%1,%2,%0;" : "+l"(d) : "l"(a), "l"(b));
}
__device__ __forceinline__ uint32_t s2u(const void* p) {
    return (uint32_t)__cvta_generic_to_shared(p);
}
__device__ __forceinline__ void cpa4(uint32_t s, const float* g) {
    asm volatile("cp.async.ca.shared.global [%0],[%1],4;" :: "r"(s), "l"(g));
}
__device__ __forceinline__ void cpa16(uint32_t s, const void* g) {
    asm volatile("cp.async.cg.shared.global [%0],[%1],16;" :: "r"(s), "l"(g));
}
__device__ __forceinline__ void cpa_commit() { asm volatile("cp.async.commit_group;"); }
template <int N> __device__ __forceinline__ void cpa_wait() {
    asm volatile("cp.async.wait_group %0;" :: "n"(N));
}
__device__ __forceinline__ unsigned long long lds64(const float* p) {
    unsigned long long v;
    asm("ld.shared.b64 %0,[%1];" : "=l"(v) : "r"(s2u(p)));
    return v;
}
__device__ __forceinline__ uint32_t lds32(uint32_t a) {
    uint32_t v;
    asm("ld.shared.b32 %0,[%1];" : "=r"(v) : "r"(a));
    return v;
}
// mma.sync bf16 (sm_80+, works on compute_103 virtual arch)
__device__ __forceinline__ void mma_bf16(float* c, const uint32_t* a, const uint32_t* b) {
    asm volatile(
        "mma.sync.aligned.m16n8k16.row.col.f32.bf16.bf16.f32 "
        "{%0,%1,%2,%3},{%4,%5,%6,%7},{%8,%9},{%0,%1,%2,%3};"
        : "+f"(c[0]), "+f"(c[1]), "+f"(c[2]), "+f"(c[3])
        : "r"(a[0]), "r"(a[1]), "r"(a[2]), "r"(a[3]), "r"(b[0]), "r"(b[1]));
}

// ---------------- 1. W_enc -> bf16 hi/lo, k-major, padded to 320x320 -----------
__global__ void wtrans_enc(const float* __restrict__ Wenc) {
    int rel = blockIdx.y;
    int tid = threadIdx.x;
    if (blockIdx.x == 0 && rel == 0 && tid < 9) g_cnt[tid] = 0;
    int base = blockIdx.x * 512 + tid * 2;
#pragma unroll
    for (int q = 0; q < 2; q++) {
        int e = base + q;
        int f = e / 320, k = e - f * 320;
        float v = (f < 300 && k < 300) ? Wenc[((size_t)rel * 300 + f) * 300 + k] : 0.f;
        __nv_bfloat16 hi = __float2bfloat16(v);
        __nv_bfloat16 lo = __float2bfloat16(v - __bfloat162float(hi));
        g_WencK[((size_t)(rel * 2 + 0) * 320 + f) * 320 + k] = hi;
        g_WencK[((size_t)(rel * 2 + 1) * 320 + f) * 320 + k] = lo;
    }
}

// ---------------- 2. fp32 MLP weight transpose+pair+pad -------------------------
__global__ void wtrans_all(const float* __restrict__ W0, const float* __restrict__ W1,
                           const float* __restrict__ W2) {
    int kt = blockIdx.x, j = blockIdx.y, z = blockIdx.z;   // z: 0-1 W0, 2-5 W1/W2
    int tid = threadIdx.x;
    const float* src; float* dst; int K, Kpad, fbase, sl;
    if (z < 2) { K = 1800; Kpad = 1808; sl = z;     src = W0;
                 fbase = sl * 300;       dst = g_W0T;  if (kt >= 113) return; }
    else       { K = 600;  Kpad = 608;  sl = z - 2; src = (z >= 4) ? W2 : W1;
                 fbase = (sl & 1) * 300; dst = g_W12T; if (kt >= 38)  return; }
    __shared__ float s[64][17];
    int k0 = kt * 16;
#pragma unroll
    for (int pass = 0; pass < 4; pass++) {
        int fit = pass * 16 + (tid >> 4);
        int kk = tid & 15;
        int fl = j * 64 + fit;
        int k = k0 + kk;
        float v = 0.f;
        if (fl < 300 && k < K) v = src[(size_t)(fbase + fl) * K + k];
        s[fit][kk] = v;
    }
    __syncthreads();
#pragma unroll
    for (int pass = 0; pass < 4; pass++) {
        int kin = pass * 4 + (tid >> 6);
        int q = tid & 63;
        int w = (q >> 1) + ((q & 1) << 5);
        dst[((size_t)sl * Kpad + k0 + kin) * 320 + j * 64 + q] = s[w][kin];
    }
}

// ---------------- 3. prep: embeddings + bf16 mirrors + compaction ---------------
__global__ void prep_kernel(const int* __restrict__ px, const int* __restrict__ hx,
                            const int* __restrict__ pwi, const int* __restrict__ hwi,
                            const float* __restrict__ E,
                            const int* __restrict__ prel, const int* __restrict__ hrel) {
    __shared__ int sx[64], swi[64];
    __shared__ unsigned ball[64];
    __shared__ int pref[64];
    __shared__ int sbase;
    int tid = threadIdx.x, lane = tid & 31, wid = tid >> 5;

    if (blockIdx.x < 512) {
        int b = blockIdx.x & 255, tree = blockIdx.x >> 8;
        const int* x  = (tree ? hx : px) + b * 64;
        const int* wi = (tree ? hwi : pwi) + b * 64;
        if (tid < 64) { sx[tid] = x[tid]; swi[tid] = wi[tid]; }
        __syncthreads();
        size_t row0 = (size_t)(tree * BATCH + b) * NNODE;
        float* hb = g_h + row0 * HSTR;
        __nv_bfloat16* mhi = g_hbhi + row0 * 320;
        __nv_bfloat16* mlo = g_hblo + row0 * 320;
        if (tid >= 300) {
            __nv_bfloat16 z = __float2bfloat16(0.f);
            for (int n = 0; n < 64; n++) {
                if (tid < 304) hb[n * HSTR + tid] = 0.f;
                mhi[n * 320 + tid] = z;
                mlo[n * 320 + tid] = z;
            }
            return;
        }
        float rep = 0.f;
#pragma unroll 8
        for (int s = 0; s < 64; s++) rep += __ldg(&E[(size_t)sx[s] * EMB + tid]);
        g_rep[((size_t)tree * BATCH + b) * EMB + tid] = rep;
        for (int n = 0; n < 64; n++) {
            int w = swi[n];
            float v = (w < 0) ? 1.0f : __ldg(&E[(size_t)sx[w] * EMB + tid]);
            hb[n * HSTR + tid] = v;
            __nv_bfloat16 hi = __float2bfloat16(v);
            mhi[n * 320 + tid] = hi;
            mlo[n * 320 + tid] = __float2bfloat16(v - __bfloat162float(hi));
        }
        return;
    }

    int cb = blockIdx.x - 512;
    int li = cb % 9, chunk = cb / 9;
    int l = li / 3, r = li % 3;
    int n0, nc;
    if (l == 0)      { n0 = 1;  nc = 4;  }
    else if (l == 1) { n0 = 5;  nc = 16; }
    else             { n0 = 21; nc = 43; }
    int total = 512 * nc;
    int base = chunk * 2048;
    if (base >= total) return;
    if (tid < 256) {
#pragma unroll
        for (int it = 0; it < 8; it++) {
            int i = base + it * 256 + tid;
            int flag = 0;
            if (i < total) {
                int tb = i / nc;
                int n = n0 + (i - tb * nc);
                int tree = tb >> 8, b = tb & 255;
                flag = ((tree ? hrel : prel)[b * 64 + n] == r);
            }
            unsigned m = __ballot_sync(0xffffffffu, flag);
            if (lane == 0) ball[wid * 8 + it] = m;
        }
    }
    __syncthreads();
    if (tid == 0) {
        int run = 0;
        for (int s = 0; s < 64; s++) { pref[s] = run; run += __popc(ball[s]); }
        sbase = atomicAdd(&g_cnt[li], run);
    }
    __syncthreads();
    if (tid < 256) {
#pragma unroll
        for (int it = 0; it < 8; it++) {
            int i = base + it * 256 + tid;
            int flag = 0, v = 0;
            if (i < total) {
                int tb = i / nc;
                int n = n0 + (i - tb * nc);
                int tree = tb >> 8, b = tb & 255;
                flag = ((tree ? hrel : prel)[b * 64 + n] == r);
                v = (tb << 6) | n;
            }
            unsigned m = ball[wid * 8 + it];
            int within = __popc(m & ((1u << lane) - 1));
            if (flag) g_rows[li][sbase + pref[wid * 8 + it] + within] = v;
        }
    }
}

// ---------------- 4. mma.sync bf16 gathered GEMM (3xBF16 split) -----------------
// smem: A[buf][hl][128][24bf16]=2x12288, B[buf][hl][160][24]=2x15360, meta 512
// total 55808 bytes dynamic.
#define TMMA_SMEM 55808
__global__ void __launch_bounds__(256) tree_mma(int l) {
    extern __shared__ char smem[];
    int rel = blockIdx.z;
    int li = l * 3 + rel;
    int cnt = g_cnt[li];
    int row0 = blockIdx.x * 128;
    if (row0 >= cnt) return;
    int fs = blockIdx.y * 160;

    uint32_t sb = s2u(smem);
    int* meta = (int*)(smem + 55296);
    int tid = threadIdx.x, lane = tid & 31, warp = tid >> 5;
    int warp_m = warp >> 1, warp_n = warp & 1;
    if (tid < 128) {
        int rr = row0 + tid;
        meta[tid] = (rr < cnt) ? g_rows[li][rr] : -1;
    }
    __syncthreads();

    auto fill = [&](int c, int buf) {
        int k0 = c * 16;
        for (int i = tid; i < 1152; i += 256) {
            if (i < 512) {
                int hl = i >> 8, j = i & 255, m = j >> 1, half = j & 1;
                int mm = meta[m];
                const void* src = (mm < 0) ? (const void*)g_zero
                    : (const void*)((hl ? g_hblo : g_hbhi) + (size_t)mm * 320 + k0 + half * 8);
                cpa16(sb + (uint32_t)(buf * 12288 + hl * 6144 + m * 48 + half * 16), src);
            } else {
                int i2 = i - 512;
                int hl = (i2 >= 320);
                int j = i2 - (hl ? 320 : 0);
                int n = j >> 1, half = j & 1;
                const __nv_bfloat16* src =
                    g_WencK + ((size_t)(rel * 2 + hl) * 320 + fs + n) * 320 + k0 + half * 8;
                cpa16(sb + (uint32_t)(24576 + buf * 15360 + hl * 7680 + n * 48 + half * 16), src);
            }
        }
        cpa_commit();
    };

    float C[2][10][4];
#pragma unroll
    for (int mi = 0; mi < 2; mi++)
#pragma unroll
        for (int ni = 0; ni < 10; ni++)
#pragma unroll
            for (int q = 0; q < 4; q++) C[mi][ni][q] = 0.f;

    fill(0, 0);
    for (int t = 0; t < 20; t++) {
        int buf = t & 1;
        if (t < 19) { fill(t + 1, buf ^ 1); cpa_wait<1>(); }
        else        { cpa_wait<0>(); }
        __syncthreads();

        uint32_t abase = sb + (uint32_t)(buf * 12288 + (warp_m * 32 + (lane >> 2)) * 48
                                         + (lane & 3) * 4);
        uint32_t Ah[2][4], Al[2][4];
#pragma unroll
        for (int mi = 0; mi < 2; mi++) {
            uint32_t a0 = abase + mi * 768;           // +16 rows
            Ah[mi][0] = lds32(a0);
            Ah[mi][1] = lds32(a0 + 384);              // +8 rows
            Ah[mi][2] = lds32(a0 + 16);               // +8 cols
            Ah[mi][3] = lds32(a0 + 400);
            uint32_t a1 = a0 + 6144;                  // lo plane
            Al[mi][0] = lds32(a1);
            Al[mi][1] = lds32(a1 + 384);
            Al[mi][2] = lds32(a1 + 16);
            Al[mi][3] = lds32(a1 + 400);
        }
        uint32_t bbase = sb + (uint32_t)(24576 + buf * 15360
                                         + (warp_n * 80 + (lane >> 2)) * 48 + (lane & 3) * 4);
#pragma unroll
        for (int ni = 0; ni < 10; ni++) {
            uint32_t b0 = bbase + ni * 384;           // +8 n-rows
            uint32_t Bh[2] = { lds32(b0), lds32(b0 + 16) };
            uint32_t Bl[2] = { lds32(b0 + 7680), lds32(b0 + 7696) };
#pragma unroll
            for (int mi = 0; mi < 2; mi++) {
                mma_bf16(C[mi][ni], Ah[mi], Bh);      // hi*hi
                mma_bf16(C[mi][ni], Ah[mi], Bl);      // hi*lo
                mma_bf16(C[mi][ni], Al[mi], Bh);      // lo*hi
            }
        }
        __syncthreads();
    }

    // epilogue: scatter C to g_t rows (f32, stride HSTR)
#pragma unroll
    for (int mi = 0; mi < 2; mi++) {
        int r0 = warp_m * 32 + mi * 16 + (lane >> 2);
        int mmA = meta[r0], mmB = meta[r0 + 8];
#pragma unroll
        for (int ni = 0; ni < 10; ni++) {
            int f = fs + warp_n * 80 + ni * 8 + (lane & 3) * 2;
            if (f < 300) {
                if (mmA >= 0)
                    *(float2*)(g_t + (size_t)mmA * HSTR + f) =
                        make_float2(C[mi][ni][0], C[mi][ni][1]);
                if (mmB >= 0)
                    *(float2*)(g_t + (size_t)mmB * HSTR + f) =
                        make_float2(C[mi][ni][2], C[mi][ni][3]);
            }
        }
    }
}

// ---------------- 5. combine (float4) + bf16 mirror refresh ---------------------
__global__ void update_kernel(const int* __restrict__ prel, const int* __restrict__ hrel,
                              int plo) {
    int p = plo + blockIdx.x;
    int b = blockIdx.y, tree = blockIdx.z;
    int e4 = threadIdx.x;
    if (e4 >= 76) return;
    const int* rel = (tree ? hrel : prel) + b * 64;
    size_t rbase = (size_t)(tree * BATCH + b) * NNODE;
    size_t base = rbase * HSTR;
    const float4* hb = (const float4*)(g_h + base);
    const float4* tb = (const float4*)(g_t + base);
    int c0 = 4 * p + 1;
    int c1 = 4 * p + 4; if (c1 > 63) c1 = 63;
    float4 s = make_float4(0.f, 0.f, 0.f, 0.f);
#pragma unroll
    for (int c = c0; c <= c1; c++) {
        if (c > 63) break;
        unsigned rid = (unsigned)rel[c];
        const float4* src = (rid <= 2u) ? tb : hb;
        float4 v = src[c * 76 + e4];
        s.x += v.x; s.y += v.y; s.z += v.z; s.w += v.w;
    }
    float cntf = (float)(c1 - c0 + 1);
    float4 hp = hb[p * 76 + e4];
    float4 o;
    o.x = fmaxf(hp.x * (s.x / cntf), 0.f);
    o.y = fmaxf(hp.y * (s.y / cntf), 0.f);
    o.z = fmaxf(hp.z * (s.z / cntf), 0.f);
    o.w = fmaxf(hp.w * (s.w / cntf), 0.f);
    ((float4*)(g_h + base))[p * 76 + e4] = o;
    __nv_bfloat16* mhi = g_hbhi + (rbase + p) * 320 + 4 * e4;
    __nv_bfloat16* mlo = g_hblo + (rbase + p) * 320 + 4 * e4;
    float vv[4] = {o.x, o.y, o.z, o.w};
#pragma unroll
    for (int q = 0; q < 4; q++) {
        __nv_bfloat16 hi = __float2bfloat16(vv[q]);
        mhi[q] = hi;
        mlo[q] = __float2bfloat16(vv[q] - __bfloat162float(hi));
    }
}

// ---------------- 6. fused root update + MLP input build ------------------------
__global__ void update1_buildx(const int* __restrict__ prel, const int* __restrict__ hrel) {
    int b = blockIdx.x;
    int e = threadIdx.x;
    __shared__ float root[2][300];
#pragma unroll
    for (int tree = 0; tree < 2; tree++) {
        if (e < 300) {
            const int* rel = (tree ? hrel : prel) + b * 64;
            size_t base = ((size_t)(tree * BATCH + b) * NNODE) * HSTR;
            const float* hb = g_h + base;
            const float* tb = g_t + base;
            float s = 0.f;
#pragma unroll
            for (int c = 1; c <= 4; c++) {
                unsigned rid = (unsigned)rel[c];
                s += (rid <= 2u) ? tb[c * HSTR + e] : hb[c * HSTR + e];
            }
            float v = hb[e] * (s * 0.25f);
            root[tree][e] = fmaxf(v, 0.f);
        }
    }
    __syncthreads();
    if (e >= 300) return;
    float pr = g_rep[b * EMB + e];
    float hr = g_rep[(BATCH + b) * EMB + e];
    float ps = root[0][e], hs = root[1][e];
    float* x = g_x + (size_t)b * 1808;
    x[e] = pr; x[300 + e] = hr; x[600 + e] = pr - hr; x[900 + e] = pr * hr;
    x[1200 + e] = ps - hs; x[1500 + e] = ps * hs;
}

// ---------------- 7. MLP GEMM (fp32 FFMA2, paired, double-buffered) -------------
__global__ void __launch_bounds__(256) fc_gemm(int sel, int kpad, int ksl) {
    const float* A  = (sel == 0) ? g_x : (sel == 1) ? g_y0 : g_y1;
    const float* Wt = (sel == 0) ? g_W0T : (sel == 1) ? g_W12T : (g_W12T + 2 * 608 * 320);
    float* out = (sel == 0) ? g_acc0 : (sel == 1) ? g_acc1 : g_acc2;
    int m0 = blockIdx.x * 32;
    int fs2 = blockIdx.y;
    int z = blockIdx.z;
    int kbeg = z * ksl;
    int kend = kbeg + ksl; if (kend > kpad) kend = kpad;
    int nt = (kend - kbeg) >> 4;
    const float* Wsl = Wt + (size_t)fs2 * kpad * 320;

    __shared__ float As2[2][32][16][2];
    __shared__ float Ws[2][16][320];
    int tid = threadIdx.x, lane = tid & 31, warp = tid >> 5;

    uint32_t asu[2] = { s2u(&As2[0][0][0][0]), s2u(&As2[1][0][0][0]) };
    uint32_t wsu[2] = { s2u(&Ws[0][0][0]), s2u(&Ws[1][0][0]) };

    auto fill = [&](int t, int buf) {
        int k0 = kbeg + t * 16;
#pragma unroll
        for (int i = tid; i < 512; i += 256) {
            int m = i >> 4, kk = i & 15;
            const float* src = A + (size_t)(m0 + m) * kpad + k0 + kk;
            uint32_t d = asu[buf] + (uint32_t)(i << 3);
            cpa4(d, src); cpa4(d + 4, src);
        }
        const float* wsrc = Wsl + (size_t)k0 * 320;
#pragma unroll
        for (int i = tid; i < 1280; i += 256)
            cpa16(wsu[buf] + (uint32_t)(i << 4), wsrc + (i << 2));
        cpa_commit();
    };

    unsigned long long acc[4][5];
#pragma unroll
    for (int i = 0; i < 4; i++)
#pragma unroll
        for (int j = 0; j < 5; j++) acc[i][j] = 0ull;

    fill(0, 0);
    for (int t = 0; t < nt; t++) {
        int buf = t & 1;
        if (t < nt - 1) { fill(t + 1, buf ^ 1); cpa_wait<1>(); }
        else            { cpa_wait<0>(); }
        __syncthreads();
#pragma unroll
        for (int kk = 0; kk < 16; kk++) {
            unsigned long long w2[5];
#pragma unroll
            for (int j = 0; j < 5; j++)
                w2[j] = lds64(&Ws[buf][kk][(j * 32 + lane) * 2]);
#pragma unroll
            for (int i = 0; i < 4; i++) {
                unsigned long long a2 = lds64(&As2[buf][warp * 4 + i][kk][0]);
#pragma unroll
                for (int j = 0; j < 5; j++) ffma2(acc[i][j], a2, w2[j]);
            }
        }
        __syncthreads();
    }

#pragma unroll
    for (int i = 0; i < 4; i++) {
        float* o = out + (size_t)z * BATCH * 600 + (size_t)(m0 + warp * 4 + i) * 600 + fs2 * 300;
#pragma unroll
        for (int j = 0; j < 5; j++) {
            float lo, hi; upk(acc[i][j], lo, hi);
            int f0 = lane + 64 * j;
            o[f0] = lo;
            if (f0 + 32 < 300) o[f0 + 32] = hi;
        }
    }
}

// ---------------- 8. reduce k-split slabs + bias + relu -------------------------
__global__ void bias_relu_kernel(const float* __restrict__ bias, int sel, int nz) {
    int b = blockIdx.x, n = threadIdx.x;
    const float* acc = (sel == 0) ? g_acc0 : g_acc1;
    float s = bias[n];
    for (int z = 0; z < nz; z++) s += acc[(size_t)z * BATCH * 600 + b * 600 + n];
    float* y = (sel == 0) ? g_y0 : g_y1;
    y[b * 608 + n] = s > 0.f ? s : 0.f;
}

// ---------------- 9. fused layer-2 reduce + bias + relu + output ----------------
__global__ void bias2_out(const float* __restrict__ bias, const float* __restrict__ Wout,
                          const float* __restrict__ bout, float* __restrict__ out) {
    int b = blockIdx.x, n = threadIdx.x;
    __shared__ float sy[600];
    if (n < 600) {
        float s = bias[n];
        for (int z = 0; z < 8; z++) s += g_acc2[(size_t)z * BATCH * 600 + b * 600 + n];
        sy[n] = s > 0.f ? s : 0.f;
    }
    __syncthreads();
    int w = n >> 5, lane = n & 31;
    if (w >= 3) return;
    float s = 0.f;
    for (int k = lane; k < 600; k += 32)
        s += sy[k] * Wout[w * 600 + k];
    for (int o = 16; o; o >>= 1) s += __shfl_down_sync(0xffffffffu, s, o);
    if (lane == 0) out[b * 3 + w] = s + bout[w];
}

// ---------------- launch ----------------------------------------------------------
extern "C" void kernel_launch(void* const* d_in, const int* in_sizes, int n_in,
                              void* d_out, int out_size) {
    const int*   px   = (const int*)d_in[0];
    const int*   hx   = (const int*)d_in[1];
    const int*   pwi  = (const int*)d_in[2];
    const int*   prel = (const int*)d_in[3];
    const int*   hwi  = (const int*)d_in[4];
    const int*   hrel = (const int*)d_in[5];
    const float* E    = (const float*)d_in[8];
    const float* Wenc = (const float*)d_in[9];
    const float* W0w  = (const float*)d_in[10];
    const float* W0b  = (const float*)d_in[11];
    const float* W1w  = (const float*)d_in[12];
    const float* W1b  = (const float*)d_in[13];
    const float* W2w  = (const float*)d_in[14];
    const float* W2b  = (const float*)d_in[15];
    const float* Wow  = (const float*)d_in[16];
    const float* Wob  = (const float*)d_in[17];
    float* out = (float*)d_out;

    static int smem_set = 0;
    if (!smem_set) {
        cudaFuncSetAttribute(tree_mma, cudaFuncAttributeMaxDynamicSharedMemorySize, TMMA_SMEM);
        smem_set = 1;
    }

    wtrans_enc<<<dim3(200, 3), 256>>>(Wenc);                              // 1 (+zero g_cnt)
    wtrans_all<<<dim3(113, 5, 6), 256>>>(W0w, W1w, W2w);                  // 2
    prep_kernel<<<611, 320>>>(px, hx, pwi, hwi, E, prel, hrel);           // 3

    tree_mma<<<dim3(172, 2, 3), 256, TMMA_SMEM>>>(2);                     // 4
    update_kernel<<<dim3(11, 256, 2), 96>>>(prel, hrel, 5);               // 5
    tree_mma<<<dim3(64, 2, 3), 256, TMMA_SMEM>>>(1);                      // 6 <- profiled
    update_kernel<<<dim3(4, 256, 2), 96>>>(prel, hrel, 1);                // 7
    tree_mma<<<dim3(16, 2, 3), 256, TMMA_SMEM>>>(0);                      // 8
    update1_buildx<<<256, 320>>>(prel, hrel);                             // 9

    fc_gemm<<<dim3(8, 2, 10), 256>>>(0, 1808, 192);                       // 10
    bias_relu_kernel<<<256, 600>>>(W0b, 0, 10);                           // 11
    fc_gemm<<<dim3(8, 2, 8), 256>>>(1, 608, 80);                          // 12
    bias_relu_kernel<<<256, 600>>>(W1b, 1, 8);                            // 13
    fc_gemm<<<dim3(8, 2, 8), 256>>>(2, 608, 80);                          // 14
    bias2_out<<<256, 608>>>(W2b, Wow, Wob, out);                          // 15
}

// round 7
// speedup vs baseline: 3.2369x; 1.0493x over previous
#include <cuda_runtime.h>
#include <cuda_bf16.h>
#include <cstdint>

#define EMB 300
#define HSTR 304
#define BATCH 256
#define NNODE 64

// ---------------- scratch (static device memory; zero-initialized) -----------
__device__ float g_h[2 * BATCH * NNODE * HSTR];
__device__ float g_t[2 * BATCH * NNODE * HSTR];
__device__ __align__(16) __nv_bfloat16 g_hbhi[2 * BATCH * NNODE * 320];
__device__ __align__(16) __nv_bfloat16 g_hblo[2 * BATCH * NNODE * 320];
__device__ __align__(16) __nv_bfloat16 g_WencK[3 * 2 * 320 * 320]; // [rel][hi/lo][f][k]
__device__ __align__(16) float g_zero[8];                          // stays zero
__device__ float g_rep2[2][2 * BATCH * EMB];                       // rep partials
__device__ float g_x[BATCH * 1808];
__device__ float g_y0[BATCH * 608];
__device__ float g_y1[BATCH * 608];
__device__ float g_acc0[10 * BATCH * 600];
__device__ float g_acc1[8 * BATCH * 600];
__device__ float g_acc2[8 * BATCH * 600];
__device__ float g_W0T[2 * 1808 * 320];
__device__ float g_W12T[4 * 608 * 320];
__device__ int   g_rows[9][22016];
__device__ int   g_cnt[9];

// ---------------- helpers -----------------------------------------------------
__device__ __forceinline__ void upk(unsigned long long v, float& lo, float& hi) {
    asm("mov.b64 {%0,%1},%2;" : "=f"(lo), "=f"(hi) : "l"(v));
}
__device__ __forceinline__ void ffma2(unsigned long long& d, unsigned long long a,
                                      unsigned long long b) {
    asm("fma.rn.f32x2 %0,%1,%2,%0;" : "+l"(d) : "l"(a), "l"(b));
}
__device__ __forceinline__ uint32_t s2u(const void* p) {
    return (uint32_t)__cvta_generic_to_shared(p);
}
__device__ __forceinline__ void cpa4(uint32_t s, const float* g) {
    asm volatile("cp.async.ca.shared.global [%0],[%1],4;" :: "r"(s), "l"(g));
}
__device__ __forceinline__ void cpa16(uint32_t s, const void* g) {
    asm volatile("cp.async.cg.shared.global [%0],[%1],16;" :: "r"(s), "l"(g));
}
__device__ __forceinline__ void cpa_commit() { asm volatile("cp.async.commit_group;"); }
template <int N> __device__ __forceinline__ void cpa_wait() {
    asm volatile("cp.async.wait_group %0;" :: "n"(N));
}
__device__ __forceinline__ unsigned long long lds64(const float* p) {
    unsigned long long v;
    asm("ld.shared.b64 %0,[%1];" : "=l"(v) : "r"(s2u(p)));
    return v;
}
__device__ __forceinline__ uint32_t lds32(uint32_t a) {
    uint32_t v;
    asm("ld.shared.b32 %0,[%1];" : "=r"(v) : "r"(a));
    return v;
}
// mma.sync bf16 (sm_80+, works on compute_103 virtual arch)
__device__ __forceinline__ void mma_bf16(float* c, const uint32_t* a, const uint32_t* b) {
    asm volatile(
        "mma.sync.aligned.m16n8k16.row.col.f32.bf16.bf16.f32 "
        "{%0,%1,%2,%3},{%4,%5,%6,%7},{%8,%9},{%0,%1,%2,%3};"
        : "+f"(c[0]), "+f"(c[1]), "+f"(c[2]), "+f"(c[3])
        : "r"(a[0]), "r"(a[1]), "r"(a[2]), "r"(a[3]), "r"(b[0]), "r"(b[1]));
}

// ---------------- 1. W_enc -> bf16 hi/lo, k-major, padded to 320x320 -----------
__global__ void wtrans_enc(const float* __restrict__ Wenc) {
    int rel = blockIdx.y;
    int tid = threadIdx.x;
    if (blockIdx.x == 0 && rel == 0 && tid < 9) g_cnt[tid] = 0;
    int base = blockIdx.x * 512 + tid * 2;
#pragma unroll
    for (int q = 0; q < 2; q++) {
        int e = base + q;
        int f = e / 320, k = e - f * 320;
        float v = (f < 300 && k < 300) ? Wenc[((size_t)rel * 300 + f) * 300 + k] : 0.f;
        __nv_bfloat16 hi = __float2bfloat16(v);
        __nv_bfloat16 lo = __float2bfloat16(v - __bfloat162float(hi));
        g_WencK[((size_t)(rel * 2 + 0) * 320 + f) * 320 + k] = hi;
        g_WencK[((size_t)(rel * 2 + 1) * 320 + f) * 320 + k] = lo;
    }
}

// ---------------- 2. fp32 MLP weight transpose+pair+pad -------------------------
__global__ void wtrans_all(const float* __restrict__ W0, const float* __restrict__ W1,
                           const float* __restrict__ W2) {
    int kt = blockIdx.x, j = blockIdx.y, z = blockIdx.z;   // z: 0-1 W0, 2-5 W1/W2
    int tid = threadIdx.x;
    const float* src; float* dst; int K, Kpad, fbase, sl;
    if (z < 2) { K = 1800; Kpad = 1808; sl = z;     src = W0;
                 fbase = sl * 300;       dst = g_W0T;  if (kt >= 113) return; }
    else       { K = 600;  Kpad = 608;  sl = z - 2; src = (z >= 4) ? W2 : W1;
                 fbase = (sl & 1) * 300; dst = g_W12T; if (kt >= 38)  return; }
    __shared__ float s[64][17];
    int k0 = kt * 16;
#pragma unroll
    for (int pass = 0; pass < 4; pass++) {
        int fit = pass * 16 + (tid >> 4);
        int kk = tid & 15;
        int fl = j * 64 + fit;
        int k = k0 + kk;
        float v = 0.f;
        if (fl < 300 && k < K) v = src[(size_t)(fbase + fl) * K + k];
        s[fit][kk] = v;
    }
    __syncthreads();
#pragma unroll
    for (int pass = 0; pass < 4; pass++) {
        int kin = pass * 4 + (tid >> 6);
        int q = tid & 63;
        int w = (q >> 1) + ((q & 1) << 5);
        dst[((size_t)sl * Kpad + k0 + kin) * 320 + j * 64 + q] = s[w][kin];
    }
}

// ---------------- 3. prep: embeddings (split halves) + compaction ---------------
__global__ void prep_kernel(const int* __restrict__ px, const int* __restrict__ hx,
                            const int* __restrict__ pwi, const int* __restrict__ hwi,
                            const float* __restrict__ E,
                            const int* __restrict__ prel, const int* __restrict__ hrel) {
    __shared__ int sx[64], swi[64];
    __shared__ unsigned ball[64];
    __shared__ int pref[64];
    __shared__ int sbase;
    int tid = threadIdx.x, lane = tid & 31, wid = tid >> 5;

    if (blockIdx.x < 1024) {
        int half = blockIdx.x & 1;
        int b = (blockIdx.x >> 1) & 255;
        int tree = blockIdx.x >> 9;
        const int* x  = (tree ? hx : px) + b * 64;
        const int* wi = (tree ? hwi : pwi) + b * 64;
        if (tid < 64) { sx[tid] = x[tid]; swi[tid] = wi[tid]; }
        __syncthreads();
        size_t row0 = (size_t)(tree * BATCH + b) * NNODE;
        float* hb = g_h + row0 * HSTR;
        __nv_bfloat16* mhi = g_hbhi + row0 * 320;
        __nv_bfloat16* mlo = g_hblo + row0 * 320;
        int n0 = half * 32;
        if (tid >= 300) {
            __nv_bfloat16 z = __float2bfloat16(0.f);
            for (int n = n0; n < n0 + 32; n++) {
                if (tid < 304) hb[n * HSTR + tid] = 0.f;
                mhi[n * 320 + tid] = z;
                mlo[n * 320 + tid] = z;
            }
            return;
        }
        float rep = 0.f;
#pragma unroll 8
        for (int s = n0; s < n0 + 32; s++) rep += __ldg(&E[(size_t)sx[s] * EMB + tid]);
        g_rep2[half][((size_t)tree * BATCH + b) * EMB + tid] = rep;
        for (int n = n0; n < n0 + 32; n++) {
            int w = swi[n];
            float v = (w < 0) ? 1.0f : __ldg(&E[(size_t)sx[w] * EMB + tid]);
            hb[n * HSTR + tid] = v;
            __nv_bfloat16 hi = __float2bfloat16(v);
            mhi[n * 320 + tid] = hi;
            mlo[n * 320 + tid] = __float2bfloat16(v - __bfloat162float(hi));
        }
        return;
    }

    int cb = blockIdx.x - 1024;
    int li = cb % 9, chunk = cb / 9;
    int l = li / 3, r = li % 3;
    int n0, nc;
    if (l == 0)      { n0 = 1;  nc = 4;  }
    else if (l == 1) { n0 = 5;  nc = 16; }
    else             { n0 = 21; nc = 43; }
    int total = 512 * nc;
    int base = chunk * 2048;
    if (base >= total) return;
    if (tid < 256) {
#pragma unroll
        for (int it = 0; it < 8; it++) {
            int i = base + it * 256 + tid;
            int flag = 0;
            if (i < total) {
                int tb = i / nc;
                int n = n0 + (i - tb * nc);
                int tree = tb >> 8, b = tb & 255;
                flag = ((tree ? hrel : prel)[b * 64 + n] == r);
            }
            unsigned m = __ballot_sync(0xffffffffu, flag);
            if (lane == 0) ball[wid * 8 + it] = m;
        }
    }
    __syncthreads();
    if (tid == 0) {
        int run = 0;
        for (int s = 0; s < 64; s++) { pref[s] = run; run += __popc(ball[s]); }
        sbase = atomicAdd(&g_cnt[li], run);
    }
    __syncthreads();
    if (tid < 256) {
#pragma unroll
        for (int it = 0; it < 8; it++) {
            int i = base + it * 256 + tid;
            int flag = 0, v = 0;
            if (i < total) {
                int tb = i / nc;
                int n = n0 + (i - tb * nc);
                int tree = tb >> 8, b = tb & 255;
                flag = ((tree ? hrel : prel)[b * 64 + n] == r);
                v = (tb << 6) | n;
            }
            unsigned m = ball[wid * 8 + it];
            int within = __popc(m & ((1u << lane) - 1));
            if (flag) g_rows[li][sbase + pref[wid * 8 + it] + within] = v;
        }
    }
}

// ---------------- 4. mma.sync bf16 gathered GEMM (3xBF16, 128 threads) ----------
// static smem: A[buf][hl][64][24bf16]=12288, B[buf][hl][160][24]=30720, meta 256
__global__ void __launch_bounds__(128) tree_mma(int l) {
    __shared__ __align__(16) char smem[43264];
    int rel = blockIdx.z;
    int li = l * 3 + rel;
    int cnt = g_cnt[li];
    int row0 = blockIdx.x * 64;
    if (row0 >= cnt) return;
    int fs = blockIdx.y * 160;

    uint32_t sb = s2u(smem);
    int* meta = (int*)(smem + 43008);
    int tid = threadIdx.x, lane = tid & 31, warp = tid >> 5;
    int warp_m = warp >> 1, warp_n = warp & 1;
    if (tid < 64) {
        int rr = row0 + tid;
        meta[tid] = (rr < cnt) ? g_rows[li][rr] : -1;
    }
    __syncthreads();

    auto fill = [&](int c, int buf) {
        int k0 = c * 16;
        for (int i = tid; i < 896; i += 128) {
            if (i < 256) {
                int hl = i >> 7, j = i & 127, m = j >> 1, half = j & 1;
                int mm = meta[m];
                const void* src = (mm < 0) ? (const void*)g_zero
                    : (const void*)((hl ? g_hblo : g_hbhi) + (size_t)mm * 320 + k0 + half * 8);
                cpa16(sb + (uint32_t)(buf * 6144 + hl * 3072 + m * 48 + half * 16), src);
            } else {
                int i2 = i - 256;
                int hl = (i2 >= 320);
                int j = i2 - (hl ? 320 : 0);
                int n = j >> 1, half = j & 1;
                const __nv_bfloat16* src =
                    g_WencK + ((size_t)(rel * 2 + hl) * 320 + fs + n) * 320 + k0 + half * 8;
                cpa16(sb + (uint32_t)(12288 + buf * 15360 + hl * 7680 + n * 48 + half * 16), src);
            }
        }
        cpa_commit();
    };

    float C[2][10][4];
#pragma unroll
    for (int mi = 0; mi < 2; mi++)
#pragma unroll
        for (int ni = 0; ni < 10; ni++)
#pragma unroll
            for (int q = 0; q < 4; q++) C[mi][ni][q] = 0.f;

    fill(0, 0);
    for (int t = 0; t < 20; t++) {
        int buf = t & 1;
        if (t < 19) { fill(t + 1, buf ^ 1); cpa_wait<1>(); }
        else        { cpa_wait<0>(); }
        __syncthreads();

        uint32_t abase = sb + (uint32_t)(buf * 6144 + (warp_m * 32 + (lane >> 2)) * 48
                                         + (lane & 3) * 4);
        uint32_t Ah[2][4], Al[2][4];
#pragma unroll
        for (int mi = 0; mi < 2; mi++) {
            uint32_t a0 = abase + mi * 768;           // +16 rows
            Ah[mi][0] = lds32(a0);
            Ah[mi][1] = lds32(a0 + 384);              // +8 rows
            Ah[mi][2] = lds32(a0 + 16);               // +8 cols
            Ah[mi][3] = lds32(a0 + 400);
            uint32_t a1 = a0 + 3072;                  // lo plane
            Al[mi][0] = lds32(a1);
            Al[mi][1] = lds32(a1 + 384);
            Al[mi][2] = lds32(a1 + 16);
            Al[mi][3] = lds32(a1 + 400);
        }
        uint32_t bbase = sb + (uint32_t)(12288 + buf * 15360
                                         + (warp_n * 80 + (lane >> 2)) * 48 + (lane & 3) * 4);
#pragma unroll
        for (int ni = 0; ni < 10; ni++) {
            uint32_t b0 = bbase + ni * 384;           // +8 n-rows
            uint32_t Bh[2] = { lds32(b0), lds32(b0 + 16) };
            uint32_t Bl[2] = { lds32(b0 + 7680), lds32(b0 + 7696) };
#pragma unroll
            for (int mi = 0; mi < 2; mi++) {
                mma_bf16(C[mi][ni], Ah[mi], Bh);      // hi*hi
                mma_bf16(C[mi][ni], Ah[mi], Bl);      // hi*lo
                mma_bf16(C[mi][ni], Al[mi], Bh);      // lo*hi
            }
        }
        __syncthreads();
    }

    // epilogue: scatter C to g_t rows (f32, stride HSTR)
#pragma unroll
    for (int mi = 0; mi < 2; mi++) {
        int r0 = warp_m * 32 + mi * 16 + (lane >> 2);
        int mmA = meta[r0], mmB = meta[r0 + 8];
#pragma unroll
        for (int ni = 0; ni < 10; ni++) {
            int f = fs + warp_n * 80 + ni * 8 + (lane & 3) * 2;
            if (f < 300) {
                if (mmA >= 0)
                    *(float2*)(g_t + (size_t)mmA * HSTR + f) =
                        make_float2(C[mi][ni][0], C[mi][ni][1]);
                if (mmB >= 0)
                    *(float2*)(g_t + (size_t)mmB * HSTR + f) =
                        make_float2(C[mi][ni][2], C[mi][ni][3]);
            }
        }
    }
}

// ---------------- 5. combine (float4) + bf16 mirror refresh ---------------------
__global__ void update_kernel(const int* __restrict__ prel, const int* __restrict__ hrel,
                              int plo) {
    int p = plo + blockIdx.x;
    int b = blockIdx.y, tree = blockIdx.z;
    int e4 = threadIdx.x;
    if (e4 >= 76) return;
    const int* rel = (tree ? hrel : prel) + b * 64;
    size_t rbase = (size_t)(tree * BATCH + b) * NNODE;
    size_t base = rbase * HSTR;
    const float4* hb = (const float4*)(g_h + base);
    const float4* tb = (const float4*)(g_t + base);
    int c0 = 4 * p + 1;
    int c1 = 4 * p + 4; if (c1 > 63) c1 = 63;
    float4 s = make_float4(0.f, 0.f, 0.f, 0.f);
#pragma unroll
    for (int c = c0; c <= c1; c++) {
        if (c > 63) break;
        unsigned rid = (unsigned)rel[c];
        const float4* src = (rid <= 2u) ? tb : hb;
        float4 v = src[c * 76 + e4];
        s.x += v.x; s.y += v.y; s.z += v.z; s.w += v.w;
    }
    float cntf = (float)(c1 - c0 + 1);
    float4 hp = hb[p * 76 + e4];
    float4 o;
    o.x = fmaxf(hp.x * (s.x / cntf), 0.f);
    o.y = fmaxf(hp.y * (s.y / cntf), 0.f);
    o.z = fmaxf(hp.z * (s.z / cntf), 0.f);
    o.w = fmaxf(hp.w * (s.w / cntf), 0.f);
    ((float4*)(g_h + base))[p * 76 + e4] = o;
    __nv_bfloat16* mhi = g_hbhi + (rbase + p) * 320 + 4 * e4;
    __nv_bfloat16* mlo = g_hblo + (rbase + p) * 320 + 4 * e4;
    float vv[4] = {o.x, o.y, o.z, o.w};
#pragma unroll
    for (int q = 0; q < 4; q++) {
        __nv_bfloat16 hi = __float2bfloat16(vv[q]);
        mhi[q] = hi;
        mlo[q] = __float2bfloat16(vv[q] - __bfloat162float(hi));
    }
}

// ---------------- 6. fused root update + MLP input build ------------------------
__global__ void update1_buildx(const int* __restrict__ prel, const int* __restrict__ hrel) {
    int b = blockIdx.x;
    int e = threadIdx.x;
    __shared__ float root[2][300];
#pragma unroll
    for (int tree = 0; tree < 2; tree++) {
        if (e < 300) {
            const int* rel = (tree ? hrel : prel) + b * 64;
            size_t base = ((size_t)(tree * BATCH + b) * NNODE) * HSTR;
            const float* hb = g_h + base;
            const float* tb = g_t + base;
            float s = 0.f;
#pragma unroll
            for (int c = 1; c <= 4; c++) {
                unsigned rid = (unsigned)rel[c];
                s += (rid <= 2u) ? tb[c * HSTR + e] : hb[c * HSTR + e];
            }
            float v = hb[e] * (s * 0.25f);
            root[tree][e] = fmaxf(v, 0.f);
        }
    }
    __syncthreads();
    if (e >= 300) return;
    float pr = g_rep2[0][b * EMB + e] + g_rep2[1][b * EMB + e];
    float hr = g_rep2[0][(BATCH + b) * EMB + e] + g_rep2[1][(BATCH + b) * EMB + e];
    float ps = root[0][e], hs = root[1][e];
    float* x = g_x + (size_t)b * 1808;
    x[e] = pr; x[300 + e] = hr; x[600 + e] = pr - hr; x[900 + e] = pr * hr;
    x[1200 + e] = ps - hs; x[1500 + e] = ps * hs;
}

// ---------------- 7. MLP GEMM (fp32 FFMA2, paired, double-buffered) -------------
__global__ void __launch_bounds__(256) fc_gemm(int sel, int kpad, int ksl) {
    const float* A  = (sel == 0) ? g_x : (sel == 1) ? g_y0 : g_y1;
    const float* Wt = (sel == 0) ? g_W0T : (sel == 1) ? g_W12T : (g_W12T + 2 * 608 * 320);
    float* out = (sel == 0) ? g_acc0 : (sel == 1) ? g_acc1 : g_acc2;
    int m0 = blockIdx.x * 32;
    int fs2 = blockIdx.y;
    int z = blockIdx.z;
    int kbeg = z * ksl;
    int kend = kbeg + ksl; if (kend > kpad) kend = kpad;
    int nt = (kend - kbeg) >> 4;
    const float* Wsl = Wt + (size_t)fs2 * kpad * 320;

    __shared__ float As2[2][32][16][2];
    __shared__ float Ws[2][16][320];
    int tid = threadIdx.x, lane = tid & 31, warp = tid >> 5;

    uint32_t asu[2] = { s2u(&As2[0][0][0][0]), s2u(&As2[1][0][0][0]) };
    uint32_t wsu[2] = { s2u(&Ws[0][0][0]), s2u(&Ws[1][0][0]) };

    auto fill = [&](int t, int buf) {
        int k0 = kbeg + t * 16;
#pragma unroll
        for (int i = tid; i < 512; i += 256) {
            int m = i >> 4, kk = i & 15;
            const float* src = A + (size_t)(m0 + m) * kpad + k0 + kk;
            uint32_t d = asu[buf] + (uint32_t)(i << 3);
            cpa4(d, src); cpa4(d + 4, src);
        }
        const float* wsrc = Wsl + (size_t)k0 * 320;
#pragma unroll
        for (int i = tid; i < 1280; i += 256)
            cpa16(wsu[buf] + (uint32_t)(i << 4), wsrc + (i << 2));
        cpa_commit();
    };

    unsigned long long acc[4][5];
#pragma unroll
    for (int i = 0; i < 4; i++)
#pragma unroll
        for (int j = 0; j < 5; j++) acc[i][j] = 0ull;

    fill(0, 0);
    for (int t = 0; t < nt; t++) {
        int buf = t & 1;
        if (t < nt - 1) { fill(t + 1, buf ^ 1); cpa_wait<1>(); }
        else            { cpa_wait<0>(); }
        __syncthreads();
#pragma unroll
        for (int kk = 0; kk < 16; kk++) {
            unsigned long long w2[5];
#pragma unroll
            for (int j = 0; j < 5; j++)
                w2[j] = lds64(&Ws[buf][kk][(j * 32 + lane) * 2]);
#pragma unroll
            for (int i = 0; i < 4; i++) {
                unsigned long long a2 = lds64(&As2[buf][warp * 4 + i][kk][0]);
#pragma unroll
                for (int j = 0; j < 5; j++) ffma2(acc[i][j], a2, w2[j]);
            }
        }
        __syncthreads();
    }

#pragma unroll
    for (int i = 0; i < 4; i++) {
        float* o = out + (size_t)z * BATCH * 600 + (size_t)(m0 + warp * 4 + i) * 600 + fs2 * 300;
#pragma unroll
        for (int j = 0; j < 5; j++) {
            float lo, hi; upk(acc[i][j], lo, hi);
            int f0 = lane + 64 * j;
            o[f0] = lo;
            if (f0 + 32 < 300) o[f0 + 32] = hi;
        }
    }
}

// ---------------- 8. reduce k-split slabs + bias + relu -------------------------
__global__ void bias_relu_kernel(const float* __restrict__ bias, int sel, int nz) {
    int b = blockIdx.x, n = threadIdx.x;
    const float* acc = (sel == 0) ? g_acc0 : g_acc1;
    float s = bias[n];
    for (int z = 0; z < nz; z++) s += acc[(size_t)z * BATCH * 600 + b * 600 + n];
    float* y = (sel == 0) ? g_y0 : g_y1;
    y[b * 608 + n] = s > 0.f ? s : 0.f;
}

// ---------------- 9. fused layer-2 reduce + bias + relu + output ----------------
__global__ void bias2_out(const float* __restrict__ bias, const float* __restrict__ Wout,
                          const float* __restrict__ bout, float* __restrict__ out) {
    int b = blockIdx.x, n = threadIdx.x;
    __shared__ float sy[600];
    if (n < 600) {
        float s = bias[n];
        for (int z = 0; z < 8; z++) s += g_acc2[(size_t)z * BATCH * 600 + b * 600 + n];
        sy[n] = s > 0.f ? s : 0.f;
    }
    __syncthreads();
    int w = n >> 5, lane = n & 31;
    if (w >= 3) return;
    float s = 0.f;
    for (int k = lane; k < 600; k += 32)
        s += sy[k] * Wout[w * 600 + k];
    for (int o = 16; o; o >>= 1) s += __shfl_down_sync(0xffffffffu, s, o);
    if (lane == 0) out[b * 3 + w] = s + bout[w];
}

// ---------------- launch ----------------------------------------------------------
extern "C" void kernel_launch(void* const* d_in, const int* in_sizes, int n_in,
                              void* d_out, int out_size) {
    const int*   px   = (const int*)d_in[0];
    const int*   hx   = (const int*)d_in[1];
    const int*   pwi  = (const int*)d_in[2];
    const int*   prel = (const int*)d_in[3];
    const int*   hwi  = (const int*)d_in[4];
    const int*   hrel = (const int*)d_in[5];
    const float* E    = (const float*)d_in[8];
    const float* Wenc = (const float*)d_in[9];
    const float* W0w  = (const float*)d_in[10];
    const float* W0b  = (const float*)d_in[11];
    const float* W1w  = (const float*)d_in[12];
    const float* W1b  = (const float*)d_in[13];
    const float* W2w  = (const float*)d_in[14];
    const float* W2b  = (const float*)d_in[15];
    const float* Wow  = (const float*)d_in[16];
    const float* Wob  = (const float*)d_in[17];
    float* out = (float*)d_out;

    wtrans_enc<<<dim3(200, 3), 256>>>(Wenc);                              // 1 (+zero g_cnt)
    wtrans_all<<<dim3(113, 5, 6), 256>>>(W0w, W1w, W2w);                  // 2
    prep_kernel<<<1123, 320>>>(px, hx, pwi, hwi, E, prel, hrel);          // 3

    tree_mma<<<dim3(344, 2, 3), 128>>>(2);                                // 4
    update_kernel<<<dim3(11, 256, 2), 96>>>(prel, hrel, 5);               // 5
    tree_mma<<<dim3(128, 2, 3), 128>>>(1);                                // 6 <- profiled
    update_kernel<<<dim3(4, 256, 2), 96>>>(prel, hrel, 1);                // 7
    tree_mma<<<dim3(32, 2, 3), 128>>>(0);                                 // 8
    update1_buildx<<<256, 320>>>(prel, hrel);                             // 9

    fc_gemm<<<dim3(8, 2, 10), 256>>>(0, 1808, 192);                       // 10
    bias_relu_kernel<<<256, 600>>>(W0b, 0, 10);                           // 11
    fc_gemm<<<dim3(8, 2, 8), 256>>>(1, 608, 80);                          // 12
    bias_relu_kernel<<<256, 600>>>(W1b, 1, 8);                            // 13
    fc_gemm<<<dim3(8, 2, 8), 256>>>(2, 608, 80);                          // 14
    bias2_out<<<256, 608>>>(W2b, Wow, Wob, out);                          // 15
}